// round 7
// baseline (speedup 1.0000x reference)
#include <cuda_runtime.h>
#include <math.h>
#include <stdint.h>

// Problem dims
#define NB 64
#define NS 64
#define NV 32000
#define NE 768
#define NH 1024
#define NHH 768

#define GRID 192
#define TPB  256

// ---------------- scratch (device globals; no allocations allowed) ----------
__device__ float g_X    [NB*NS*NE];            // LN'd embeddings, row = s*64+b
__device__ float g_IX   [(size_t)NB*NS*3*NH];  // x_t @ Wi_x + bi, per token
__device__ float g_ILraw[NB*3*NH];             // raw ILOW = IX_t + h_h @ Wi_h
__device__ float g_HG   [NB*3*NH];             // raw h_l @ Wh + bh
__device__ float g_IHI  [NB*3*NHH];            // raw h_l @ hWi + hbi
__device__ float g_HHG  [NB*3*NHH];            // raw h_h @ hWh + hbh
__device__ float2 g_psA [3*64*64];             // partial (sum,sumsq) stats
__device__ float2 g_psB [3*64*64];
__device__ float g_hl   [NB*NH];
__device__ float g_hh   [NB*NHH];
__device__ float g_HH   [NB*NS*NHH];           // h_h history, row = t*64+b

// grid barrier state (self-resetting; generation is monotonic across replays)
__device__ unsigned g_bar = 0;
__device__ volatile unsigned g_gen = 0;

// ---------------- init: zero hidden states ----------------------------------
__global__ void k_init() {
    int i = blockIdx.x * 256 + threadIdx.x;
    if (i < NB*NH)  g_hl[i] = 0.f;
    if (i < NB*NHH) g_hh[i] = 0.f;
}

// ---------------- embedding lookup + LayerNorm ------------------------------
__global__ void k_embed(const int* __restrict__ ids, const float* __restrict__ emb,
                        const float* __restrict__ g, const float* __restrict__ bb) {
    int tok = blockIdx.x;            // tok = s*64 + b
    int b = tok & 63, s = tok >> 6;
    int id = ids[b*NS + s];
    const float* e = emb + (size_t)id * NE;
    int tid = threadIdx.x;

    __shared__ float sa[256], sb[256];
    float sum = 0.f, sq = 0.f;
    for (int j = tid; j < NE; j += 256) { float v = e[j]; sum += v; sq += v*v; }
    sa[tid] = sum; sb[tid] = sq; __syncthreads();
    for (int o = 128; o > 0; o >>= 1) {
        if (tid < o) { sa[tid] += sa[tid+o]; sb[tid] += sb[tid+o]; }
        __syncthreads();
    }
    __shared__ float s_m, s_r;
    if (tid == 0) {
        float m = sa[0] / NE;
        float var = sb[0] / NE - m*m;
        s_m = m; s_r = rsqrtf(var + 1e-5f);
    }
    __syncthreads();
    float m = s_m, r = s_r;
    float* xo = g_X + (size_t)tok * NE;
    for (int j = tid; j < NE; j += 256) {
        float v = e[j];
        xo[j] = (v - m) * r * g[j] + bb[j];
    }
}

// ---------------- big GEMM: C[M,N] = A[M,K] @ W[K,N] + bias ------------------
__global__ void k_gemm_n64(const float* __restrict__ A, const float* __restrict__ W,
                           const float* __restrict__ bias, float* __restrict__ C,
                           int K, int N, int remap) {
    __shared__ float As[32][65];
    __shared__ float Ws[32][65];
    int tid = threadIdx.x;
    int tx = tid & 31, ty = tid >> 5;
    int n0 = blockIdx.x * 64;
    int m0 = blockIdx.y * 64;
    const float* Ab = A + (size_t)m0 * K;

    float acc[8][2];
    #pragma unroll
    for (int r = 0; r < 8; r++) { acc[r][0] = 0.f; acc[r][1] = 0.f; }

    for (int k0 = 0; k0 < K; k0 += 32) {
        #pragma unroll
        for (int i = 0; i < 8; i++) {
            int r = ty + i*8;
            As[tx][r] = Ab[(size_t)r*K + k0 + tx];
        }
        #pragma unroll
        for (int i = 0; i < 4; i++) {
            int kk = ty*4 + i;
            Ws[kk][tx]      = W[(size_t)(k0 + kk)*N + n0 + tx];
            Ws[kk][tx + 32] = W[(size_t)(k0 + kk)*N + n0 + tx + 32];
        }
        __syncthreads();
        #pragma unroll
        for (int k = 0; k < 32; k++) {
            float w0 = Ws[k][tx], w1 = Ws[k][tx + 32];
            #pragma unroll
            for (int r = 0; r < 8; r++) {
                float a = As[k][ty*8 + r];
                acc[r][0] += a * w0;
                acc[r][1] += a * w1;
            }
        }
        __syncthreads();
    }
    float b0 = bias ? bias[n0 + tx]      : 0.f;
    float b1 = bias ? bias[n0 + tx + 32] : 0.f;
    #pragma unroll
    for (int r = 0; r < 8; r++) {
        int grow = m0 + ty*8 + r;
        size_t orow = remap ? (size_t)((grow & 63) * 64 + (grow >> 6)) : (size_t)grow;
        C[orow*N + n0 + tx]      = acc[r][0] + b0;
        C[orow*N + n0 + tx + 32] = acc[r][1] + b1;
    }
}

// ================= persistent recurrence kernel ==============================

__device__ __forceinline__ void gridbar() {
    __syncthreads();
    if (threadIdx.x == 0) {
        __threadfence();
        unsigned g = g_gen;
        if (atomicAdd(&g_bar, 1u) == GRID - 1) {
            g_bar = 0;
            __threadfence();
            g_gen = g + 1;
        } else {
            while (g_gen == g) { __nanosleep(64); }
        }
        __threadfence();
    }
    __syncthreads();
}

// 64xN-tile GEMM: C[64,16] tile at col n0 = A[64,K] @ W[K, n0:n0+16] (+bias)(+Add)
// Also emits per-row (sum, sumsq) partials into pst[row*64] for LN stats.
__device__ __forceinline__ void gemm_tile(
    const float* __restrict__ A, int K,
    const float* __restrict__ W, int N,
    const float* __restrict__ bias, const float* __restrict__ Add,
    float* __restrict__ C, int n0,
    float2* __restrict__ pst,
    float* __restrict__ As /*[32*68]*/, float* __restrict__ Ws /*[32*17]*/)
{
    int tid = threadIdx.x;
    int col = tid & 15, rq = tid >> 4;
    int lk  = tid & 31, lr = tid >> 5;
    int wc  = tid & 15, wk = tid >> 4;

    float a0 = 0.f, a1 = 0.f, a2 = 0.f, a3 = 0.f;

    for (int k0 = 0; k0 < K; k0 += 32) {
        #pragma unroll
        for (int i = 0; i < 8; i++)
            As[lk*68 + lr + i*8] = A[(size_t)(lr + i*8)*K + k0 + lk];
        Ws[wk*17 + wc]        = W[(size_t)(k0 + wk     )*N + n0 + wc];
        Ws[(wk + 16)*17 + wc] = W[(size_t)(k0 + wk + 16)*N + n0 + wc];
        __syncthreads();
        #pragma unroll
        for (int k = 0; k < 32; k++) {
            float4 a = *reinterpret_cast<const float4*>(As + k*68 + rq*4);
            float w = Ws[k*17 + col];
            a0 += a.x*w; a1 += a.y*w; a2 += a.z*w; a3 += a.w*w;
        }
        __syncthreads();
    }
    float bv = bias ? bias[n0 + col] : 0.f;
    int r = rq * 4;
    float o0 = a0 + bv, o1 = a1 + bv, o2 = a2 + bv, o3 = a3 + bv;
    if (Add) {
        o0 += Add[(size_t)(r  )*N + n0 + col];
        o1 += Add[(size_t)(r+1)*N + n0 + col];
        o2 += Add[(size_t)(r+2)*N + n0 + col];
        o3 += Add[(size_t)(r+3)*N + n0 + col];
    }
    C[(size_t)(r  )*N + n0 + col] = o0;
    C[(size_t)(r+1)*N + n0 + col] = o1;
    C[(size_t)(r+2)*N + n0 + col] = o2;
    C[(size_t)(r+3)*N + n0 + col] = o3;

    // per-row partial stats across the 16 cols of this tile (lanes 0..15 groups)
    float q0 = o0*o0, q1 = o1*o1, q2 = o2*o2, q3 = o3*o3;
    #pragma unroll
    for (int off = 1; off < 16; off <<= 1) {
        o0 += __shfl_xor_sync(0xffffffffu, o0, off);
        q0 += __shfl_xor_sync(0xffffffffu, q0, off);
        o1 += __shfl_xor_sync(0xffffffffu, o1, off);
        q1 += __shfl_xor_sync(0xffffffffu, q1, off);
        o2 += __shfl_xor_sync(0xffffffffu, o2, off);
        q2 += __shfl_xor_sync(0xffffffffu, q2, off);
        o3 += __shfl_xor_sync(0xffffffffu, o3, off);
        q3 += __shfl_xor_sync(0xffffffffu, q3, off);
    }
    if (col == 0) {
        pst[(r  )*64] = make_float2(o0, q0);
        pst[(r+1)*64] = make_float2(o1, q1);
        pst[(r+2)*64] = make_float2(o2, q2);
        pst[(r+3)*64] = make_float2(o3, q3);
    }
}

// warp-cooperative stats finalize: sum T partials, return (mean, rstd)
__device__ __forceinline__ float2 warp_stat(const float2* __restrict__ p, int T, float inv_hid) {
    int l = threadIdx.x & 31;
    float s = p[l].x, q = p[l].y;
    if (l + 32 < T) { s += p[l+32].x; q += p[l+32].y; }
    #pragma unroll
    for (int o = 16; o > 0; o >>= 1) {
        s += __shfl_xor_sync(0xffffffffu, s, o);
        q += __shfl_xor_sync(0xffffffffu, q, o);
    }
    float m = s * inv_hid;
    float r = rsqrtf(q * inv_hid - m*m + 1e-5f);
    return make_float2(m, r);
}

__device__ __forceinline__ float sigm(float x) { return 1.f / (1.f + expf(-x)); }

__global__ void __launch_bounds__(TPB, 2) k_recur(
    const float* __restrict__ lWi, const float* __restrict__ lbh,
    const float* __restrict__ lWh,
    const float* __restrict__ llig, const float* __restrict__ llib,
    const float* __restrict__ llhg, const float* __restrict__ llhb,
    const float* __restrict__ hWi,  const float* __restrict__ hbi,
    const float* __restrict__ hWh,  const float* __restrict__ hbh,
    const float* __restrict__ hlig, const float* __restrict__ hlib,
    const float* __restrict__ hlhg, const float* __restrict__ hlhb)
{
    __shared__ __align__(16) float As[32*68];
    __shared__ float Ws[32*17];
    __shared__ float s_st[12];

    const float* lWi_h = lWi + (size_t)NE * 3 * NH;  // rows 768..1535 of low_Wi
    int bid = blockIdx.x, tid = threadIdx.x;
    int w = tid >> 5;
    int b = bid & 63, third = bid >> 6;

    for (int t = 0; t < NS; t++) {
        const float* ixt = g_IX + (size_t)t * NB * 3 * NH;
        for (int c = 0; c < 3; c++) {
            // ---- P1: ILOW = h_h @ Wi_h + IX_t  (raw + stats into psA) -------
            gemm_tile(g_hh, NHH, lWi_h, 3*NH, nullptr, ixt,
                      g_ILraw, bid*16, g_psA + (bid>>6)*4096 + (bid & 63), As, Ws);
            gridbar();

            // ---- low-cell inner loop ----------------------------------------
            for (int u = 0; u < 5; u++) {
                // HG = h_l @ Wh + bh (raw + stats into psB)
                gemm_tile(g_hl, NH, lWh, 3*NH, lbh, nullptr,
                          g_HG, bid*16, g_psB + (bid>>6)*4096 + (bid & 63), As, Ws);
                gridbar();

                // combine: LN(IL) + LN(HG) + gates -> h_l
                if (w < 6) {
                    const float2* p = (w < 3)
                        ? g_psA + w*4096 + b*64
                        : g_psB + (w-3)*4096 + b*64;
                    float2 mr = warp_stat(p, 64, 1.f/NH);
                    if ((tid & 31) == 0) { s_st[2*w] = mr.x; s_st[2*w+1] = mr.y; }
                }
                __syncthreads();
                {
                    const float* Ib = g_ILraw + (size_t)b*3*NH;
                    const float* Hb = g_HG    + (size_t)b*3*NH;
                    int js = (third * NH) / 3, je = ((third + 1) * NH) / 3;
                    for (int j = js + tid; j < je; j += TPB) {
                        float i0 = (Ib[j       ] - s_st[0])*s_st[1]*llig[j       ] + llib[j       ];
                        float i1 = (Ib[NH  + j ] - s_st[2])*s_st[3]*llig[NH  + j ] + llib[NH  + j ];
                        float i2 = (Ib[2*NH + j] - s_st[4])*s_st[5]*llig[2*NH + j] + llib[2*NH + j];
                        float h0 = (Hb[j       ] - s_st[6])*s_st[7]*llhg[j       ] + llhb[j       ];
                        float h1 = (Hb[NH  + j ] - s_st[8])*s_st[9]*llhg[NH  + j ] + llhb[NH  + j ];
                        float h2 = (Hb[2*NH + j] - s_st[10])*s_st[11]*llhg[2*NH + j] + llhb[2*NH + j];
                        float r = sigm(i0 + h0);
                        float z = sigm(i1 + h1);
                        float n = tanhf(i2 + r*h2);
                        float hp = g_hl[(size_t)b*NH + j];
                        g_hl[(size_t)b*NH + j] = (1.f - z)*n + z*hp;
                    }
                }
                gridbar();
            }

            // ---- P5: high-cell GEMMs (288 tile jobs over 192 blocks) --------
            for (int job = bid; job < 288; job += GRID) {
                if (job < 144) {
                    gemm_tile(g_hl, NH, hWi, 3*NHH, hbi, nullptr,
                              g_IHI, job*16, g_psA + (job/48)*4096 + (job%48), As, Ws);
                } else {
                    int nt = job - 144;
                    gemm_tile(g_hh, NHH, hWh, 3*NHH, hbh, nullptr,
                              g_HHG, nt*16, g_psB + (nt/48)*4096 + (nt%48), As, Ws);
                }
            }
            gridbar();

            // ---- P6: high combine -> h_h (+history at c==2) ------------------
            if (w < 6) {
                const float2* p = (w < 3)
                    ? g_psA + w*4096 + b*64
                    : g_psB + (w-3)*4096 + b*64;
                float2 mr = warp_stat(p, 48, 1.f/NHH);
                if ((tid & 31) == 0) { s_st[2*w] = mr.x; s_st[2*w+1] = mr.y; }
            }
            __syncthreads();
            {
                const float* Ib = g_IHI + (size_t)b*3*NHH;
                const float* Hb = g_HHG + (size_t)b*3*NHH;
                int j = third*256 + tid;   // exactly covers 0..767
                float i0 = (Ib[j        ] - s_st[0])*s_st[1]*hlig[j        ] + hlib[j        ];
                float i1 = (Ib[NHH  + j ] - s_st[2])*s_st[3]*hlig[NHH  + j ] + hlib[NHH  + j ];
                float i2 = (Ib[2*NHH + j] - s_st[4])*s_st[5]*hlig[2*NHH + j] + hlib[2*NHH + j];
                float h0 = (Hb[j        ] - s_st[6])*s_st[7]*hlhg[j        ] + hlhb[j        ];
                float h1 = (Hb[NHH  + j ] - s_st[8])*s_st[9]*hlhg[NHH  + j ] + hlhb[NHH  + j ];
                float h2 = (Hb[2*NHH + j] - s_st[10])*s_st[11]*hlhg[2*NHH + j] + hlhb[2*NHH + j];
                float r = sigm(i0 + h0);
                float z = sigm(i1 + h1);
                float n = tanhf(i2 + r*h2);
                float hp = g_hh[(size_t)b*NHH + j];
                float nv = (1.f - z)*n + z*hp;
                g_hh[(size_t)b*NHH + j] = nv;
                if (c == 2) g_HH[(size_t)(t*64 + b)*NHH + j] = nv;
            }
            gridbar();
        }
    }
}

// ---------------- host orchestration ----------------------------------------
extern "C" void kernel_launch(void* const* d_in, const int* in_sizes, int n_in,
                              void* d_out, int out_size) {
    const int*   ids  = (const int*)  d_in[0];
    const float* emb  = (const float*)d_in[1];
    const float* leg  = (const float*)d_in[2];
    const float* leb  = (const float*)d_in[3];
    const float* lWi  = (const float*)d_in[4];   // [1536, 3072]
    const float* lbi  = (const float*)d_in[5];
    const float* lWh  = (const float*)d_in[6];   // [1024, 3072]
    const float* lbh  = (const float*)d_in[7];
    const float* llig = (const float*)d_in[8];
    const float* llib = (const float*)d_in[9];
    const float* llhg = (const float*)d_in[10];
    const float* llhb = (const float*)d_in[11];
    const float* hWi  = (const float*)d_in[12];  // [1024, 2304]
    const float* hbi  = (const float*)d_in[13];
    const float* hWh  = (const float*)d_in[14];  // [768, 2304]
    const float* hbh  = (const float*)d_in[15];
    const float* hlig = (const float*)d_in[16];
    const float* hlib = (const float*)d_in[17];
    const float* hlhg = (const float*)d_in[18];
    const float* hlhb = (const float*)d_in[19];
    const float* Wout = (const float*)d_in[20];  // [768, 32000]
    const float* bout = (const float*)d_in[21];
    float* out = (float*)d_out;

    float *pX, *pIX, *pHH;
    cudaGetSymbolAddress((void**)&pX,  g_X);
    cudaGetSymbolAddress((void**)&pIX, g_IX);
    cudaGetSymbolAddress((void**)&pHH, g_HH);

    // zero hidden states
    k_init<<<256, 256>>>();

    // x = LN(emb[ids]) laid out [S, B, E]
    k_embed<<<NB*NS, 256>>>(ids, emb, leg, leb);

    // IX = x @ Wi_x + bi for ALL tokens up front (reused 15x per step)
    k_gemm_n64<<<dim3((3*NH)/64, (NB*NS)/64), 256>>>(pX, lWi, lbi, pIX, NE, 3*NH, 0);

    // full recurrence in ONE persistent kernel (software grid barriers)
    k_recur<<<GRID, TPB>>>(lWi, lbh, lWh,
                           llig, llib, llhg, llhb,
                           hWi, hbi, hWh, hbh,
                           hlig, hlib, hlhg, hlhb);

    // logits = h_h_hist @ Wout + bout, row remap (s*64+b) -> out[(b*64+s)*V]
    k_gemm_n64<<<dim3(NV/64, (NB*NS)/64), 256>>>(pHH, Wout, bout, out, NHH, NV, 1);
}

// round 8
// speedup vs baseline: 1.3001x; 1.3001x over previous
#include <cuda_runtime.h>
#include <math.h>
#include <stdint.h>

// Problem dims
#define NB 64
#define NS 64
#define NV 32000
#define NE 768
#define NH 1024
#define NHH 768

#define GRID 192
#define TPB  128

// ---------------- scratch (device globals; no allocations allowed) ----------
__device__ float g_X    [NB*NS*NE];            // LN'd embeddings, row = s*64+b
__device__ float g_IX   [(size_t)NB*NS*3*NH];  // x_t @ Wi_x + bi, per token
__device__ float g_ILraw[NB*3*NH];             // raw ILOW = IX_t + h_h @ Wi_h
__device__ float g_HG   [NB*3*NH];             // raw h_l @ Wh + bh
__device__ float g_IHI  [NB*3*NHH];            // raw h_l @ hWi + hbi
__device__ float g_HHG  [NB*3*NHH];            // raw h_h @ hWh + hbh
__device__ float2 g_psA [3*64*64];             // partial (sum,sumsq) stats
__device__ float2 g_psB [3*64*64];
__device__ float g_hlT  [NH*64];               // h_l transposed [j][b]
__device__ float g_hhT  [NHH*64];              // h_h transposed [j][b]
__device__ float g_HH   [NB*NS*NHH];           // h_h history, row = t*64+b

// grid barrier state (self-resetting; generation is monotonic across replays)
__device__ unsigned g_bar = 0;
__device__ volatile unsigned g_gen = 0;

// ---------------- f32x2 helpers ---------------------------------------------
__device__ __forceinline__ unsigned long long fma2(unsigned long long a,
                                                   unsigned long long b,
                                                   unsigned long long c) {
    unsigned long long d;
    asm("fma.rn.f32x2 %0, %1, %2, %3;" : "=l"(d) : "l"(a), "l"(b), "l"(c));
    return d;
}
__device__ __forceinline__ unsigned long long pk2(float x) {
    unsigned long long d;
    asm("mov.b64 %0, {%1, %1};" : "=l"(d) : "f"(x));
    return d;
}
__device__ __forceinline__ void unpk(unsigned long long v, float& lo, float& hi) {
    asm("mov.b64 {%0, %1}, %2;" : "=f"(lo), "=f"(hi) : "l"(v));
}
__device__ __forceinline__ void cpa16(unsigned dst, const void* src) {
    asm volatile("cp.async.cg.shared.global [%0], [%1], 16;" :: "r"(dst), "l"(src));
}

// ---------------- init: zero hidden states (transposed layouts) -------------
__global__ void k_init() {
    int i = blockIdx.x * 256 + threadIdx.x;
    if (i < NH*64)  g_hlT[i] = 0.f;
    if (i < NHH*64) g_hhT[i] = 0.f;
}

// ---------------- embedding lookup + LayerNorm ------------------------------
__global__ void k_embed(const int* __restrict__ ids, const float* __restrict__ emb,
                        const float* __restrict__ g, const float* __restrict__ bb) {
    int tok = blockIdx.x;            // tok = s*64 + b
    int b = tok & 63, s = tok >> 6;
    int id = ids[b*NS + s];
    const float* e = emb + (size_t)id * NE;
    int tid = threadIdx.x;

    __shared__ float sa[256], sb[256];
    float sum = 0.f, sq = 0.f;
    for (int j = tid; j < NE; j += 256) { float v = e[j]; sum += v; sq += v*v; }
    sa[tid] = sum; sb[tid] = sq; __syncthreads();
    for (int o = 128; o > 0; o >>= 1) {
        if (tid < o) { sa[tid] += sa[tid+o]; sb[tid] += sb[tid+o]; }
        __syncthreads();
    }
    __shared__ float s_m, s_r;
    if (tid == 0) {
        float m = sa[0] / NE;
        float var = sb[0] / NE - m*m;
        s_m = m; s_r = rsqrtf(var + 1e-5f);
    }
    __syncthreads();
    float m = s_m, r = s_r;
    float* xo = g_X + (size_t)tok * NE;
    for (int j = tid; j < NE; j += 256) {
        float v = e[j];
        xo[j] = (v - m) * r * g[j] + bb[j];
    }
}

// ---------------- big GEMM (f32x2): C[M,N]=A[M,K]@W[K,N]+bias ----------------
// 64x64 tile, 256 threads, thread -> 4 row-pairs x 2 cols (f32x2 accumulators).
__global__ void k_gemm_n64(const float* __restrict__ A, const float* __restrict__ W,
                           const float* __restrict__ bias, float* __restrict__ C,
                           int K, int N, int remap) {
    __shared__ __align__(16) float As[32][68];
    __shared__ float Ws[32][65];
    int tid = threadIdx.x;
    int tx = tid & 31, ty = tid >> 5;
    int n0 = blockIdx.x * 64;
    int m0 = blockIdx.y * 64;
    const float* Ab = A + (size_t)m0 * K;

    unsigned long long acc[4][2];
    #pragma unroll
    for (int j = 0; j < 4; j++) { acc[j][0] = 0ull; acc[j][1] = 0ull; }

    for (int k0 = 0; k0 < K; k0 += 32) {
        #pragma unroll
        for (int i = 0; i < 8; i++) {
            int r = ty + i*8;
            As[tx][r] = Ab[(size_t)r*K + k0 + tx];
        }
        #pragma unroll
        for (int i = 0; i < 4; i++) {
            int kk = ty*4 + i;
            Ws[kk][tx]      = W[(size_t)(k0 + kk)*N + n0 + tx];
            Ws[kk][tx + 32] = W[(size_t)(k0 + kk)*N + n0 + tx + 32];
        }
        __syncthreads();
        #pragma unroll
        for (int k = 0; k < 32; k++) {
            ulonglong2 aA = *reinterpret_cast<const ulonglong2*>(&As[k][ty*8]);
            ulonglong2 aB = *reinterpret_cast<const ulonglong2*>(&As[k][ty*8 + 4]);
            unsigned long long w0 = pk2(Ws[k][tx]);
            unsigned long long w1 = pk2(Ws[k][tx + 32]);
            acc[0][0] = fma2(aA.x, w0, acc[0][0]);
            acc[0][1] = fma2(aA.x, w1, acc[0][1]);
            acc[1][0] = fma2(aA.y, w0, acc[1][0]);
            acc[1][1] = fma2(aA.y, w1, acc[1][1]);
            acc[2][0] = fma2(aB.x, w0, acc[2][0]);
            acc[2][1] = fma2(aB.x, w1, acc[2][1]);
            acc[3][0] = fma2(aB.y, w0, acc[3][0]);
            acc[3][1] = fma2(aB.y, w1, acc[3][1]);
        }
        __syncthreads();
    }
    float b0 = bias ? bias[n0 + tx]      : 0.f;
    float b1 = bias ? bias[n0 + tx + 32] : 0.f;
    #pragma unroll
    for (int j = 0; j < 4; j++) {
        float lo0, hi0, lo1, hi1;
        unpk(acc[j][0], lo0, hi0);
        unpk(acc[j][1], lo1, hi1);
        int ga = m0 + ty*8 + 2*j, gb = ga + 1;
        size_t ra = remap ? (size_t)((ga & 63)*64 + (ga >> 6)) : (size_t)ga;
        size_t rb = remap ? (size_t)((gb & 63)*64 + (gb >> 6)) : (size_t)gb;
        C[ra*N + n0 + tx]      = lo0 + b0;
        C[rb*N + n0 + tx]      = hi0 + b0;
        C[ra*N + n0 + tx + 32] = lo1 + b1;
        C[rb*N + n0 + tx + 32] = hi1 + b1;
    }
}

// ================= persistent recurrence kernel ==============================

__device__ __forceinline__ void gridbar() {
    __syncthreads();
    if (threadIdx.x == 0) {
        __threadfence();
        unsigned g = g_gen;
        if (atomicAdd(&g_bar, 1u) == GRID - 1) {
            g_bar = 0;
            __threadfence();
            g_gen = g + 1;
        } else {
            while (g_gen == g) { __nanosleep(64); }
        }
        __threadfence();
    }
    __syncthreads();
}

// 64x16-col tile GEMM with f32x2 + cp.async double buffering.
// AT: transposed A [K][64]. C[64,16] tile at col n0 = A@W (+bias)(+Add).
// Emits per-row (sum,sumsq) partials into pst[row*64].
// sm: 5120 floats (As 2x2048, Ws 2x512).
__device__ __forceinline__ void gemm16(
    const float* __restrict__ AT, int K,
    const float* __restrict__ W, int N, int n0,
    const float* __restrict__ bias, const float* __restrict__ Add,
    float* __restrict__ C, float2* __restrict__ pst,
    float* __restrict__ sm)
{
    int tid = threadIdx.x;
    int col = tid & 15, q = tid >> 4;      // col 0..15, q 0..7 (8 rows each)
    unsigned smA = (unsigned)__cvta_generic_to_shared(sm);
    unsigned smW = (unsigned)__cvta_generic_to_shared(sm + 4096);
    int nc = K >> 5;

    unsigned long long a0 = 0ull, a1 = 0ull, a2 = 0ull, a3 = 0ull;

    // prefetch chunk 0
    {
        #pragma unroll
        for (int ii = 0; ii < 4; ii++) {
            int u = tid + 128*ii;
            cpa16(smA + u*16, AT + u*4);
        }
        int wk = tid >> 2, wc4 = tid & 3;
        cpa16(smW + tid*16, W + (size_t)wk*N + n0 + wc4*4);
        asm volatile("cp.async.commit_group;");
    }
    for (int ch = 0; ch < nc; ch++) {
        if (ch + 1 < nc) {
            int k0 = (ch + 1) << 5;
            int bs = (ch + 1) & 1;
            const float* aseg = AT + (size_t)k0*64;
            #pragma unroll
            for (int ii = 0; ii < 4; ii++) {
                int u = tid + 128*ii;
                cpa16(smA + bs*8192 + u*16, aseg + u*4);
            }
            int wk = tid >> 2, wc4 = tid & 3;
            cpa16(smW + bs*2048 + tid*16, W + (size_t)(k0 + wk)*N + n0 + wc4*4);
            asm volatile("cp.async.commit_group;");
            asm volatile("cp.async.wait_group 1;");
        } else {
            asm volatile("cp.async.wait_group 0;");
        }
        __syncthreads();
        const float* As  = sm + (ch & 1)*2048;
        const float* Wsb = sm + 4096 + (ch & 1)*512;
        #pragma unroll
        for (int k = 0; k < 32; k++) {
            ulonglong2 aA = *reinterpret_cast<const ulonglong2*>(As + k*64 + q*8);
            ulonglong2 aB = *reinterpret_cast<const ulonglong2*>(As + k*64 + q*8 + 4);
            unsigned long long w2 = pk2(Wsb[k*16 + col]);
            a0 = fma2(aA.x, w2, a0);
            a1 = fma2(aA.y, w2, a1);
            a2 = fma2(aB.x, w2, a2);
            a3 = fma2(aB.y, w2, a3);
        }
        __syncthreads();
    }
    // epilogue
    float o[8];
    unpk(a0, o[0], o[1]);
    unpk(a1, o[2], o[3]);
    unpk(a2, o[4], o[5]);
    unpk(a3, o[6], o[7]);
    float bv = bias ? bias[n0 + col] : 0.f;
    int r0 = q * 8;
    #pragma unroll
    for (int i = 0; i < 8; i++) {
        float v = o[i] + bv;
        if (Add) v += Add[(size_t)(r0 + i)*N + n0 + col];
        o[i] = v;
        C[(size_t)(r0 + i)*N + n0 + col] = v;
    }
    #pragma unroll
    for (int i = 0; i < 8; i++) {
        float s = o[i], qq = o[i]*o[i];
        #pragma unroll
        for (int m = 1; m < 16; m <<= 1) {
            s  += __shfl_xor_sync(0xffffffffu, s,  m);
            qq += __shfl_xor_sync(0xffffffffu, qq, m);
        }
        if (col == 0) pst[(r0 + i)*64] = make_float2(s, qq);
    }
}

// warp-cooperative stats finalize: sum T partials, return (mean, rstd)
__device__ __forceinline__ float2 warp_stat(const float2* __restrict__ p, int T, float inv_hid) {
    int l = threadIdx.x & 31;
    float s = p[l].x, q = p[l].y;
    if (l + 32 < T) { s += p[l+32].x; q += p[l+32].y; }
    #pragma unroll
    for (int o = 16; o > 0; o >>= 1) {
        s += __shfl_xor_sync(0xffffffffu, s, o);
        q += __shfl_xor_sync(0xffffffffu, q, o);
    }
    float m = s * inv_hid;
    float r = rsqrtf(q * inv_hid - m*m + 1e-5f);
    return make_float2(m, r);
}

__device__ __forceinline__ float sigm(float x) { return 1.f / (1.f + expf(-x)); }

__global__ void __launch_bounds__(TPB, 2) k_recur(
    const float* __restrict__ lWi, const float* __restrict__ lbh,
    const float* __restrict__ lWh,
    const float* __restrict__ llig, const float* __restrict__ llib,
    const float* __restrict__ llhg, const float* __restrict__ llhb,
    const float* __restrict__ hWi,  const float* __restrict__ hbi,
    const float* __restrict__ hWh,  const float* __restrict__ hbh,
    const float* __restrict__ hlig, const float* __restrict__ hlib,
    const float* __restrict__ hlhg, const float* __restrict__ hlhb)
{
    __shared__ __align__(16) float sm[5120];
    __shared__ float s_st[12];

    const float* lWi_h = lWi + (size_t)NE * 3 * NH;  // rows 768..1535 of low_Wi
    int bid = blockIdx.x, tid = threadIdx.x;
    int w = tid >> 5;
    int b = bid & 63, third = bid >> 6;

    for (int t = 0; t < NS; t++) {
        const float* ixt = g_IX + (size_t)t * NB * 3 * NH;
        for (int c = 0; c < 3; c++) {
            // ---- phase A: HG(u=0) + ILOW (both depend only on current state)
            gemm16(g_hlT, NH, lWh, 3*NH, bid*16, lbh, nullptr,
                   g_HG, g_psB + (bid>>6)*4096 + (bid & 63), sm);
            gemm16(g_hhT, NHH, lWi_h, 3*NH, bid*16, nullptr, ixt,
                   g_ILraw, g_psA + (bid>>6)*4096 + (bid & 63), sm);
            gridbar();

            // ---- low-cell inner loop ----------------------------------------
            for (int u = 0; u < 5; u++) {
                // combine: LN(IL) + LN(HG) + gates -> h_lT
                for (int s = w; s < 6; s += 4) {
                    const float2* p = (s < 3)
                        ? g_psA + s*4096 + b*64
                        : g_psB + (s-3)*4096 + b*64;
                    float2 mr = warp_stat(p, 64, 1.f/NH);
                    if ((tid & 31) == 0) { s_st[2*s] = mr.x; s_st[2*s+1] = mr.y; }
                }
                __syncthreads();
                {
                    const float* Ib = g_ILraw + (size_t)b*3*NH;
                    const float* Hb = g_HG    + (size_t)b*3*NH;
                    int js = (third * NH) / 3, je = ((third + 1) * NH) / 3;
                    for (int j = js + tid; j < je; j += TPB) {
                        float i0 = (Ib[j       ] - s_st[0])*s_st[1]*llig[j       ] + llib[j       ];
                        float i1 = (Ib[NH  + j ] - s_st[2])*s_st[3]*llig[NH  + j ] + llib[NH  + j ];
                        float i2 = (Ib[2*NH + j] - s_st[4])*s_st[5]*llig[2*NH + j] + llib[2*NH + j];
                        float h0 = (Hb[j       ] - s_st[6])*s_st[7]*llhg[j       ] + llhb[j       ];
                        float h1 = (Hb[NH  + j ] - s_st[8])*s_st[9]*llhg[NH  + j ] + llhb[NH  + j ];
                        float h2 = (Hb[2*NH + j] - s_st[10])*s_st[11]*llhg[2*NH + j] + llhb[2*NH + j];
                        float r = sigm(i0 + h0);
                        float z = sigm(i1 + h1);
                        float n = tanhf(i2 + r*h2);
                        float hp = g_hlT[(size_t)j*64 + b];
                        g_hlT[(size_t)j*64 + b] = (1.f - z)*n + z*hp;
                    }
                }
                gridbar();
                if (u < 4) {
                    gemm16(g_hlT, NH, lWh, 3*NH, bid*16, lbh, nullptr,
                           g_HG, g_psB + (bid>>6)*4096 + (bid & 63), sm);
                    gridbar();
                }
            }

            // ---- high-cell GEMMs (288 tile jobs over 192 blocks) ------------
            for (int job = bid; job < 288; job += GRID) {
                if (job < 144) {
                    gemm16(g_hlT, NH, hWi, 3*NHH, job*16, hbi, nullptr,
                           g_IHI, g_psA + (job/48)*4096 + (job%48), sm);
                } else {
                    int nt = job - 144;
                    gemm16(g_hhT, NHH, hWh, 3*NHH, nt*16, hbh, nullptr,
                           g_HHG, g_psB + (nt/48)*4096 + (nt%48), sm);
                }
            }
            gridbar();

            // ---- high combine -> h_hT (+history at c==2) --------------------
            for (int s = w; s < 6; s += 4) {
                const float2* p = (s < 3)
                    ? g_psA + s*4096 + b*64
                    : g_psB + (s-3)*4096 + b*64;
                float2 mr = warp_stat(p, 48, 1.f/NHH);
                if ((tid & 31) == 0) { s_st[2*s] = mr.x; s_st[2*s+1] = mr.y; }
            }
            __syncthreads();
            {
                const float* Ib = g_IHI + (size_t)b*3*NHH;
                const float* Hb = g_HHG + (size_t)b*3*NHH;
                for (int j = third*256 + tid; j < third*256 + 256; j += TPB) {
                    float i0 = (Ib[j        ] - s_st[0])*s_st[1]*hlig[j        ] + hlib[j        ];
                    float i1 = (Ib[NHH  + j ] - s_st[2])*s_st[3]*hlig[NHH  + j ] + hlib[NHH  + j ];
                    float i2 = (Ib[2*NHH + j] - s_st[4])*s_st[5]*hlig[2*NHH + j] + hlib[2*NHH + j];
                    float h0 = (Hb[j        ] - s_st[6])*s_st[7]*hlhg[j        ] + hlhb[j        ];
                    float h1 = (Hb[NHH  + j ] - s_st[8])*s_st[9]*hlhg[NHH  + j ] + hlhb[NHH  + j ];
                    float h2 = (Hb[2*NHH + j] - s_st[10])*s_st[11]*hlhg[2*NHH + j] + hlhb[2*NHH + j];
                    float r = sigm(i0 + h0);
                    float z = sigm(i1 + h1);
                    float n = tanhf(i2 + r*h2);
                    float hp = g_hhT[(size_t)j*64 + b];
                    float nv = (1.f - z)*n + z*hp;
                    g_hhT[(size_t)j*64 + b] = nv;
                    if (c == 2) g_HH[(size_t)(t*64 + b)*NHH + j] = nv;
                }
            }
            gridbar();
        }
    }
}

// ---------------- host orchestration ----------------------------------------
extern "C" void kernel_launch(void* const* d_in, const int* in_sizes, int n_in,
                              void* d_out, int out_size) {
    const int*   ids  = (const int*)  d_in[0];
    const float* emb  = (const float*)d_in[1];
    const float* leg  = (const float*)d_in[2];
    const float* leb  = (const float*)d_in[3];
    const float* lWi  = (const float*)d_in[4];   // [1536, 3072]
    const float* lbi  = (const float*)d_in[5];
    const float* lWh  = (const float*)d_in[6];   // [1024, 3072]
    const float* lbh  = (const float*)d_in[7];
    const float* llig = (const float*)d_in[8];
    const float* llib = (const float*)d_in[9];
    const float* llhg = (const float*)d_in[10];
    const float* llhb = (const float*)d_in[11];
    const float* hWi  = (const float*)d_in[12];  // [1024, 2304]
    const float* hbi  = (const float*)d_in[13];
    const float* hWh  = (const float*)d_in[14];  // [768, 2304]
    const float* hbh  = (const float*)d_in[15];
    const float* hlig = (const float*)d_in[16];
    const float* hlib = (const float*)d_in[17];
    const float* hlhg = (const float*)d_in[18];
    const float* hlhb = (const float*)d_in[19];
    const float* Wout = (const float*)d_in[20];  // [768, 32000]
    const float* bout = (const float*)d_in[21];
    float* out = (float*)d_out;

    float *pX, *pIX, *pHH;
    cudaGetSymbolAddress((void**)&pX,  g_X);
    cudaGetSymbolAddress((void**)&pIX, g_IX);
    cudaGetSymbolAddress((void**)&pHH, g_HH);

    // zero hidden states (transposed layouts)
    k_init<<<256, 256>>>();

    // x = LN(emb[ids]) laid out [S, B, E]
    k_embed<<<NB*NS, 256>>>(ids, emb, leg, leb);

    // IX = x @ Wi_x + bi for ALL tokens up front (reused 15x per step)
    k_gemm_n64<<<dim3((3*NH)/64, (NB*NS)/64), 256>>>(pX, lWi, lbi, pIX, NE, 3*NH, 0);

    // full recurrence in ONE persistent kernel (software grid barriers)
    k_recur<<<GRID, TPB>>>(lWi, lbh, lWh,
                           llig, llib, llhg, llhb,
                           hWi, hbi, hWh, hbh,
                           hlig, hlib, hlhg, hlhb);

    // logits = h_h_hist @ Wout + bout, row remap (s*64+b) -> out[(b*64+s)*V]
    k_gemm_n64<<<dim3(NV/64, (NB*NS)/64), 256>>>(pHH, Wout, bout, out, NHH, NV, 1);
}

// round 9
// speedup vs baseline: 1.4066x; 1.0819x over previous
#include <cuda_runtime.h>
#include <math.h>
#include <stdint.h>

// Problem dims
#define NB 64
#define NS 64
#define NV 32000
#define NE 768
#define NH 1024
#define NHH 768

#define GRID 192
#define TPB  256

// ---------------- scratch (device globals; no allocations allowed) ----------
__device__ float g_X    [NB*NS*NE];            // LN'd embeddings, row = s*64+b
__device__ float g_IX   [(size_t)NB*NS*3*NH];  // x_t @ Wi_x + bi, per token
__device__ float g_ILraw[NB*3*NH];             // raw ILOW = IX_t + h_h @ Wi_h
__device__ float g_HG   [NB*3*NH];             // raw h_l @ Wh + bh
__device__ float g_IHI  [NB*3*NHH];            // raw h_l @ hWi + hbi
__device__ float g_HHG  [NB*3*NHH];            // raw h_h @ hWh + hbh
__device__ float2 g_psA [3*64*64];             // partial (sum,sumsq) stats
__device__ float2 g_psB [3*64*64];
__device__ float g_hlT  [NH*64];               // h_l transposed [j][b]
__device__ float g_hhT  [NHH*64];              // h_h transposed [j][b]
__device__ float g_HH   [NB*NS*NHH];           // h_h history, row = t*64+b

// grid barrier state (self-resetting; generation is monotonic across replays)
__device__ unsigned g_bar = 0;
__device__ volatile unsigned g_gen = 0;

// ---------------- f32x2 helpers ---------------------------------------------
__device__ __forceinline__ unsigned long long fma2(unsigned long long a,
                                                   unsigned long long b,
                                                   unsigned long long c) {
    unsigned long long d;
    asm("fma.rn.f32x2 %0, %1, %2, %3;" : "=l"(d) : "l"(a), "l"(b), "l"(c));
    return d;
}
__device__ __forceinline__ unsigned long long pk2(float x) {
    unsigned long long d;
    asm("mov.b64 %0, {%1, %1};" : "=l"(d) : "f"(x));
    return d;
}
__device__ __forceinline__ void unpk(unsigned long long v, float& lo, float& hi) {
    asm("mov.b64 {%0, %1}, %2;" : "=f"(lo), "=f"(hi) : "l"(v));
}
__device__ __forceinline__ void cpa16(unsigned dst, const void* src) {
    asm volatile("cp.async.cg.shared.global [%0], [%1], 16;" :: "r"(dst), "l"(src));
}

// ---------------- init: zero hidden states (transposed layouts) -------------
__global__ void k_init() {
    int i = blockIdx.x * 256 + threadIdx.x;
    if (i < NH*64)  g_hlT[i] = 0.f;
    if (i < NHH*64) g_hhT[i] = 0.f;
}

// ---------------- embedding lookup + LayerNorm ------------------------------
__global__ void k_embed(const int* __restrict__ ids, const float* __restrict__ emb,
                        const float* __restrict__ g, const float* __restrict__ bb) {
    int tok = blockIdx.x;            // tok = s*64 + b
    int b = tok & 63, s = tok >> 6;
    int id = ids[b*NS + s];
    const float* e = emb + (size_t)id * NE;
    int tid = threadIdx.x;

    __shared__ float sa[256], sb[256];
    float sum = 0.f, sq = 0.f;
    for (int j = tid; j < NE; j += 256) { float v = e[j]; sum += v; sq += v*v; }
    sa[tid] = sum; sb[tid] = sq; __syncthreads();
    for (int o = 128; o > 0; o >>= 1) {
        if (tid < o) { sa[tid] += sa[tid+o]; sb[tid] += sb[tid+o]; }
        __syncthreads();
    }
    __shared__ float s_m, s_r;
    if (tid == 0) {
        float m = sa[0] / NE;
        float var = sb[0] / NE - m*m;
        s_m = m; s_r = rsqrtf(var + 1e-5f);
    }
    __syncthreads();
    float m = s_m, r = s_r;
    float* xo = g_X + (size_t)tok * NE;
    for (int j = tid; j < NE; j += 256) {
        float v = e[j];
        xo[j] = (v - m) * r * g[j] + bb[j];
    }
}

// ---------------- big GEMM (f32x2): C[M,N]=A[M,K]@W[K,N]+bias ----------------
// 64x64 tile, 256 threads, thread -> 4 row-pairs x 2 cols (f32x2 accumulators).
__global__ void k_gemm_n64(const float* __restrict__ A, const float* __restrict__ W,
                           const float* __restrict__ bias, float* __restrict__ C,
                           int K, int N, int remap) {
    __shared__ __align__(16) float As[32][68];
    __shared__ float Ws[32][65];
    int tid = threadIdx.x;
    int tx = tid & 31, ty = tid >> 5;
    int n0 = blockIdx.x * 64;
    int m0 = blockIdx.y * 64;
    const float* Ab = A + (size_t)m0 * K;

    unsigned long long acc[4][2];
    #pragma unroll
    for (int j = 0; j < 4; j++) { acc[j][0] = 0ull; acc[j][1] = 0ull; }

    for (int k0 = 0; k0 < K; k0 += 32) {
        #pragma unroll
        for (int i = 0; i < 8; i++) {
            int r = ty + i*8;
            As[tx][r] = Ab[(size_t)r*K + k0 + tx];
        }
        #pragma unroll
        for (int i = 0; i < 4; i++) {
            int kk = ty*4 + i;
            Ws[kk][tx]      = W[(size_t)(k0 + kk)*N + n0 + tx];
            Ws[kk][tx + 32] = W[(size_t)(k0 + kk)*N + n0 + tx + 32];
        }
        __syncthreads();
        #pragma unroll
        for (int k = 0; k < 32; k++) {
            ulonglong2 aA = *reinterpret_cast<const ulonglong2*>(&As[k][ty*8]);
            ulonglong2 aB = *reinterpret_cast<const ulonglong2*>(&As[k][ty*8 + 4]);
            unsigned long long w0 = pk2(Ws[k][tx]);
            unsigned long long w1 = pk2(Ws[k][tx + 32]);
            acc[0][0] = fma2(aA.x, w0, acc[0][0]);
            acc[0][1] = fma2(aA.x, w1, acc[0][1]);
            acc[1][0] = fma2(aA.y, w0, acc[1][0]);
            acc[1][1] = fma2(aA.y, w1, acc[1][1]);
            acc[2][0] = fma2(aB.x, w0, acc[2][0]);
            acc[2][1] = fma2(aB.x, w1, acc[2][1]);
            acc[3][0] = fma2(aB.y, w0, acc[3][0]);
            acc[3][1] = fma2(aB.y, w1, acc[3][1]);
        }
        __syncthreads();
    }
    float b0 = bias ? bias[n0 + tx]      : 0.f;
    float b1 = bias ? bias[n0 + tx + 32] : 0.f;
    #pragma unroll
    for (int j = 0; j < 4; j++) {
        float lo0, hi0, lo1, hi1;
        unpk(acc[j][0], lo0, hi0);
        unpk(acc[j][1], lo1, hi1);
        int ga = m0 + ty*8 + 2*j, gb = ga + 1;
        size_t ra = remap ? (size_t)((ga & 63)*64 + (ga >> 6)) : (size_t)ga;
        size_t rb = remap ? (size_t)((gb & 63)*64 + (gb >> 6)) : (size_t)gb;
        C[ra*N + n0 + tx]      = lo0 + b0;
        C[rb*N + n0 + tx]      = hi0 + b0;
        C[ra*N + n0 + tx + 32] = lo1 + b1;
        C[rb*N + n0 + tx + 32] = hi1 + b1;
    }
}

// ================= persistent recurrence kernel ==============================

__device__ __forceinline__ void gridbar() {
    __syncthreads();
    if (threadIdx.x == 0) {
        __threadfence();
        unsigned g = g_gen;
        if (atomicAdd(&g_bar, 1u) == GRID - 1) {
            g_bar = 0;
            __threadfence();
            g_gen = g + 1;
        } else {
            while (g_gen == g) { __nanosleep(64); }
        }
        __threadfence();
    }
    __syncthreads();
}

// 64x16-col tile GEMM, K split across two 128-thread halves, f32x2 + cp.async
// double buffering. AT: transposed A [K][64]. C tile at col n0 (+bias)(+Add).
// Emits per-row (sum,sumsq) partials into pst[row*64].
// sm layout (floats): [0,4096) A half0 (2 bufs x 2048), [4096,8192) A half1,
// [8192,9216) W half0 (2 x 512) -- aliased as red0 in epilogue,
// [9216,10240) W half1 (2 x 512) -- aliased as red1 in epilogue.
__device__ __forceinline__ void gemm16(
    const float* __restrict__ AT, int K,
    const float* __restrict__ W, int N, int n0,
    const float* __restrict__ bias, const float* __restrict__ Add,
    float* __restrict__ C, float2* __restrict__ pst,
    float* __restrict__ sm)
{
    int tid = threadIdx.x;
    int half = tid >> 7;                 // 0 or 1: K-range owner
    int lt   = tid & 127;
    int col  = lt & 15, q = lt >> 4;     // col 0..15, q 0..7 (8 rows each)
    int Kh = K >> 1;
    int nc = Kh >> 5;
    const float* ATh = AT + (size_t)half * Kh * 64;
    const float* Whf = W  + (size_t)half * Kh * N;
    float* Abase = sm + half * 4096;
    float* Wbase = sm + 8192 + half * 1024;
    unsigned smA = (unsigned)__cvta_generic_to_shared(Abase);
    unsigned smW = (unsigned)__cvta_generic_to_shared(Wbase);

    unsigned long long a0 = 0ull, a1 = 0ull, a2 = 0ull, a3 = 0ull;

    // prefetch chunk 0 (this half's K-range)
    #pragma unroll
    for (int ii = 0; ii < 4; ii++)
        cpa16(smA + (lt + 128*ii)*16, ATh + (size_t)(lt + 128*ii)*4);
    {
        int wk = lt >> 2, wc4 = lt & 3;
        cpa16(smW + lt*16, Whf + (size_t)wk*N + n0 + wc4*4);
    }
    asm volatile("cp.async.commit_group;");

    for (int ch = 0; ch < nc; ch++) {
        if (ch + 1 < nc) {
            int k0 = (ch + 1) << 5;
            int bs = (ch + 1) & 1;
            const float* aseg = ATh + (size_t)k0 * 64;
            #pragma unroll
            for (int ii = 0; ii < 4; ii++)
                cpa16(smA + bs*8192 + (lt + 128*ii)*16, aseg + (size_t)(lt + 128*ii)*4);
            int wk = lt >> 2, wc4 = lt & 3;
            cpa16(smW + bs*2048 + lt*16, Whf + (size_t)(k0 + wk)*N + n0 + wc4*4);
            asm volatile("cp.async.commit_group;");
            asm volatile("cp.async.wait_group 1;");
        } else {
            asm volatile("cp.async.wait_group 0;");
        }
        asm volatile("bar.sync %0, 128;" :: "r"(half + 1) : "memory");
        const float* As  = Abase + (ch & 1)*2048;
        const float* Wsb = Wbase + (ch & 1)*512;
        #pragma unroll
        for (int k = 0; k < 32; k++) {
            ulonglong2 aA = *reinterpret_cast<const ulonglong2*>(As + k*64 + q*8);
            ulonglong2 aB = *reinterpret_cast<const ulonglong2*>(As + k*64 + q*8 + 4);
            unsigned long long w2 = pk2(Wsb[k*16 + col]);
            a0 = fma2(aA.x, w2, a0);
            a1 = fma2(aA.y, w2, a1);
            a2 = fma2(aB.x, w2, a2);
            a3 = fma2(aB.y, w2, a3);
        }
        asm volatile("bar.sync %0, 128;" :: "r"(half + 1) : "memory");
    }

    // dump partials to smem (alias this half's dead W buffers)
    float o[8];
    unpk(a0, o[0], o[1]);
    unpk(a1, o[2], o[3]);
    unpk(a2, o[4], o[5]);
    unpk(a3, o[6], o[7]);
    {
        float* red = sm + 8192 + half*1024;
        #pragma unroll
        for (int i = 0; i < 8; i++)
            red[(q*8 + i)*16 + col] = o[i];
    }
    __syncthreads();

    // all 256 threads finish 4 rows each: sum halves, bias/Add, store, stats
    {
        int c2 = tid & 15, q4 = tid >> 4;   // q4 0..15 -> rows q4*4..q4*4+3
        float bv = bias ? bias[n0 + c2] : 0.f;
        const float* r0p = sm + 8192;
        const float* r1p = sm + 9216;
        #pragma unroll
        for (int i = 0; i < 4; i++) {
            int r = q4*4 + i;
            float v = r0p[r*16 + c2] + r1p[r*16 + c2] + bv;
            if (Add) v += Add[(size_t)r*N + n0 + c2];
            C[(size_t)r*N + n0 + c2] = v;
            float s = v, qq = v*v;
            #pragma unroll
            for (int m = 1; m < 16; m <<= 1) {
                s  += __shfl_xor_sync(0xffffffffu, s,  m);
                qq += __shfl_xor_sync(0xffffffffu, qq, m);
            }
            if (c2 == 0) pst[r*64] = make_float2(s, qq);
        }
    }
    __syncthreads();
}

// warp-cooperative stats finalize: sum T partials, return (mean, rstd)
__device__ __forceinline__ float2 warp_stat(const float2* __restrict__ p, int T, float inv_hid) {
    int l = threadIdx.x & 31;
    float s = p[l].x, q = p[l].y;
    if (l + 32 < T) { s += p[l+32].x; q += p[l+32].y; }
    #pragma unroll
    for (int o = 16; o > 0; o >>= 1) {
        s += __shfl_xor_sync(0xffffffffu, s, o);
        q += __shfl_xor_sync(0xffffffffu, q, o);
    }
    float m = s * inv_hid;
    float r = rsqrtf(q * inv_hid - m*m + 1e-5f);
    return make_float2(m, r);
}

__device__ __forceinline__ float sigm(float x) { return 1.f / (1.f + expf(-x)); }

__global__ void __launch_bounds__(TPB, 2) k_recur(
    const float* __restrict__ lWi, const float* __restrict__ lbh,
    const float* __restrict__ lWh,
    const float* __restrict__ llig, const float* __restrict__ llib,
    const float* __restrict__ llhg, const float* __restrict__ llhb,
    const float* __restrict__ hWi,  const float* __restrict__ hbi,
    const float* __restrict__ hWh,  const float* __restrict__ hbh,
    const float* __restrict__ hlig, const float* __restrict__ hlib,
    const float* __restrict__ hlhg, const float* __restrict__ hlhb)
{
    __shared__ __align__(16) float sm[10240];
    __shared__ float s_st[12];

    const float* lWi_h = lWi + (size_t)NE * 3 * NH;  // rows 768..1535 of low_Wi
    int bid = blockIdx.x, tid = threadIdx.x;
    int w = tid >> 5;
    int b = bid & 63, third = bid >> 6;

    for (int t = 0; t < NS; t++) {
        const float* ixt = g_IX + (size_t)t * NB * 3 * NH;
        for (int c = 0; c < 3; c++) {
            // ---- phase A: HG(u=0) + ILOW (both depend only on current state)
            gemm16(g_hlT, NH, lWh, 3*NH, bid*16, lbh, nullptr,
                   g_HG, g_psB + (bid>>6)*4096 + (bid & 63), sm);
            gemm16(g_hhT, NHH, lWi_h, 3*NH, bid*16, nullptr, ixt,
                   g_ILraw, g_psA + (bid>>6)*4096 + (bid & 63), sm);
            gridbar();

            // ---- low-cell inner loop ----------------------------------------
            for (int u = 0; u < 5; u++) {
                // combine: LN(IL) + LN(HG) + gates -> h_lT
                for (int s = w; s < 6; s += 8) {
                    const float2* p = (s < 3)
                        ? g_psA + s*4096 + b*64
                        : g_psB + (s-3)*4096 + b*64;
                    float2 mr = warp_stat(p, 64, 1.f/NH);
                    if ((tid & 31) == 0) { s_st[2*s] = mr.x; s_st[2*s+1] = mr.y; }
                }
                __syncthreads();
                {
                    const float* Ib = g_ILraw + (size_t)b*3*NH;
                    const float* Hb = g_HG    + (size_t)b*3*NH;
                    int js = (third * NH) / 3, je = ((third + 1) * NH) / 3;
                    for (int j = js + tid; j < je; j += TPB) {
                        float i0 = (Ib[j       ] - s_st[0])*s_st[1]*llig[j       ] + llib[j       ];
                        float i1 = (Ib[NH  + j ] - s_st[2])*s_st[3]*llig[NH  + j ] + llib[NH  + j ];
                        float i2 = (Ib[2*NH + j] - s_st[4])*s_st[5]*llig[2*NH + j] + llib[2*NH + j];
                        float h0 = (Hb[j       ] - s_st[6])*s_st[7]*llhg[j       ] + llhb[j       ];
                        float h1 = (Hb[NH  + j ] - s_st[8])*s_st[9]*llhg[NH  + j ] + llhb[NH  + j ];
                        float h2 = (Hb[2*NH + j] - s_st[10])*s_st[11]*llhg[2*NH + j] + llhb[2*NH + j];
                        float r = sigm(i0 + h0);
                        float z = sigm(i1 + h1);
                        float n = tanhf(i2 + r*h2);
                        float hp = g_hlT[(size_t)j*64 + b];
                        g_hlT[(size_t)j*64 + b] = (1.f - z)*n + z*hp;
                    }
                }
                gridbar();
                if (u < 4) {
                    gemm16(g_hlT, NH, lWh, 3*NH, bid*16, lbh, nullptr,
                           g_HG, g_psB + (bid>>6)*4096 + (bid & 63), sm);
                    gridbar();
                }
            }

            // ---- high-cell GEMMs (288 tile jobs over 192 blocks) ------------
            for (int job = bid; job < 288; job += GRID) {
                if (job < 144) {
                    gemm16(g_hlT, NH, hWi, 3*NHH, job*16, hbi, nullptr,
                           g_IHI, g_psA + (job/48)*4096 + (job%48), sm);
                } else {
                    int nt = job - 144;
                    gemm16(g_hhT, NHH, hWh, 3*NHH, nt*16, hbh, nullptr,
                           g_HHG, g_psB + (nt/48)*4096 + (nt%48), sm);
                }
            }
            gridbar();

            // ---- high combine -> h_hT (+history at c==2) --------------------
            for (int s = w; s < 6; s += 8) {
                const float2* p = (s < 3)
                    ? g_psA + s*4096 + b*64
                    : g_psB + (s-3)*4096 + b*64;
                float2 mr = warp_stat(p, 48, 1.f/NHH);
                if ((tid & 31) == 0) { s_st[2*s] = mr.x; s_st[2*s+1] = mr.y; }
            }
            __syncthreads();
            {
                const float* Ib = g_IHI + (size_t)b*3*NHH;
                const float* Hb = g_HHG + (size_t)b*3*NHH;
                for (int j = third*256 + tid; j < third*256 + 256; j += TPB) {
                    float i0 = (Ib[j        ] - s_st[0])*s_st[1]*hlig[j        ] + hlib[j        ];
                    float i1 = (Ib[NHH  + j ] - s_st[2])*s_st[3]*hlig[NHH  + j ] + hlib[NHH  + j ];
                    float i2 = (Ib[2*NHH + j] - s_st[4])*s_st[5]*hlig[2*NHH + j] + hlib[2*NHH + j];
                    float h0 = (Hb[j        ] - s_st[6])*s_st[7]*hlhg[j        ] + hlhb[j        ];
                    float h1 = (Hb[NHH  + j ] - s_st[8])*s_st[9]*hlhg[NHH  + j ] + hlhb[NHH  + j ];
                    float h2 = (Hb[2*NHH + j] - s_st[10])*s_st[11]*hlhg[2*NHH + j] + hlhb[2*NHH + j];
                    float r = sigm(i0 + h0);
                    float z = sigm(i1 + h1);
                    float n = tanhf(i2 + r*h2);
                    float hp = g_hhT[(size_t)j*64 + b];
                    float nv = (1.f - z)*n + z*hp;
                    g_hhT[(size_t)j*64 + b] = nv;
                    if (c == 2) g_HH[(size_t)(t*64 + b)*NHH + j] = nv;
                }
            }
            gridbar();
        }
    }
}

// ---------------- host orchestration ----------------------------------------
extern "C" void kernel_launch(void* const* d_in, const int* in_sizes, int n_in,
                              void* d_out, int out_size) {
    const int*   ids  = (const int*)  d_in[0];
    const float* emb  = (const float*)d_in[1];
    const float* leg  = (const float*)d_in[2];
    const float* leb  = (const float*)d_in[3];
    const float* lWi  = (const float*)d_in[4];   // [1536, 3072]
    const float* lbi  = (const float*)d_in[5];
    const float* lWh  = (const float*)d_in[6];   // [1024, 3072]
    const float* lbh  = (const float*)d_in[7];
    const float* llig = (const float*)d_in[8];
    const float* llib = (const float*)d_in[9];
    const float* llhg = (const float*)d_in[10];
    const float* llhb = (const float*)d_in[11];
    const float* hWi  = (const float*)d_in[12];  // [1024, 2304]
    const float* hbi  = (const float*)d_in[13];
    const float* hWh  = (const float*)d_in[14];  // [768, 2304]
    const float* hbh  = (const float*)d_in[15];
    const float* hlig = (const float*)d_in[16];
    const float* hlib = (const float*)d_in[17];
    const float* hlhg = (const float*)d_in[18];
    const float* hlhb = (const float*)d_in[19];
    const float* Wout = (const float*)d_in[20];  // [768, 32000]
    const float* bout = (const float*)d_in[21];
    float* out = (float*)d_out;

    float *pX, *pIX, *pHH;
    cudaGetSymbolAddress((void**)&pX,  g_X);
    cudaGetSymbolAddress((void**)&pIX, g_IX);
    cudaGetSymbolAddress((void**)&pHH, g_HH);

    // zero hidden states (transposed layouts)
    k_init<<<256, 256>>>();

    // x = LN(emb[ids]) laid out [S, B, E]
    k_embed<<<NB*NS, 256>>>(ids, emb, leg, leb);

    // IX = x @ Wi_x + bi for ALL tokens up front (reused 15x per step)
    k_gemm_n64<<<dim3((3*NH)/64, (NB*NS)/64), 256>>>(pX, lWi, lbi, pIX, NE, 3*NH, 0);

    // full recurrence in ONE persistent kernel (software grid barriers)
    k_recur<<<GRID, TPB>>>(lWi, lbh, lWh,
                           llig, llib, llhg, llhb,
                           hWi, hbi, hWh, hbh,
                           hlig, hlib, hlhg, hlhb);

    // logits = h_h_hist @ Wout + bout, row remap (s*64+b) -> out[(b*64+s)*V]
    k_gemm_n64<<<dim3(NV/64, (NB*NS)/64), 256>>>(pHH, Wout, bout, out, NHH, NV, 1);
}

// round 10
// speedup vs baseline: 1.8756x; 1.3335x over previous
#include <cuda_runtime.h>
#include <math.h>
#include <stdint.h>

// Problem dims
#define NB 64
#define NS 64
#define NV 32000
#define NE 768
#define NH 1024
#define NHH 768

#define GRID 192
#define TPB  256

// ---------------- scratch (device globals; no allocations allowed) ----------
__device__ float g_X    [NB*NS*NE];            // LN'd embeddings, row = s*64+b
__device__ float g_IX   [(size_t)NB*NS*3*NH];  // x_t @ Wi_x + bi, per token
__device__ float g_ILraw[NB*3*NH];             // raw ILOW = IX_t + h_h @ Wi_h
__device__ float g_HG   [NB*3*NH];             // raw h_l @ Wh + bh
__device__ float g_IHI  [NB*3*NHH];            // raw h_l @ hWi + hbi
__device__ float g_HHG  [NB*3*NHH];            // raw h_h @ hWh + hbh
__device__ float2 g_psA [3*64*64];             // partial (sum,sumsq) stats
__device__ float2 g_psB [3*64*64];
__device__ float g_hlT  [NH*64];               // h_l transposed [j][b]
__device__ float g_hhT  [NHH*64];              // h_h transposed [j][b]
__device__ float g_HH   [NB*NS*NHH];           // h_h history, row = t*64+b

// grid barrier state (self-resetting; generation is monotonic across replays)
__device__ unsigned g_bar = 0;
__device__ volatile unsigned g_gen = 0;

// ---------------- f32x2 helpers ---------------------------------------------
__device__ __forceinline__ unsigned long long fma2(unsigned long long a,
                                                   unsigned long long b,
                                                   unsigned long long c) {
    unsigned long long d;
    asm("fma.rn.f32x2 %0, %1, %2, %3;" : "=l"(d) : "l"(a), "l"(b), "l"(c));
    return d;
}
__device__ __forceinline__ unsigned long long pk2(float x) {
    unsigned long long d;
    asm("mov.b64 %0, {%1, %1};" : "=l"(d) : "f"(x));
    return d;
}
__device__ __forceinline__ void unpk(unsigned long long v, float& lo, float& hi) {
    asm("mov.b64 {%0, %1}, %2;" : "=f"(lo), "=f"(hi) : "l"(v));
}
__device__ __forceinline__ void cpa16(unsigned dst, const void* src) {
    asm volatile("cp.async.cg.shared.global [%0], [%1], 16;" :: "r"(dst), "l"(src));
}

// ---------------- init: zero hidden states (transposed layouts) -------------
__global__ void k_init() {
    int i = blockIdx.x * 256 + threadIdx.x;
    if (i < NH*64)  g_hlT[i] = 0.f;
    if (i < NHH*64) g_hhT[i] = 0.f;
}

// ---------------- embedding lookup + LayerNorm ------------------------------
__global__ void k_embed(const int* __restrict__ ids, const float* __restrict__ emb,
                        const float* __restrict__ g, const float* __restrict__ bb) {
    int tok = blockIdx.x;            // tok = s*64 + b
    int b = tok & 63, s = tok >> 6;
    int id = ids[b*NS + s];
    const float* e = emb + (size_t)id * NE;
    int tid = threadIdx.x;

    __shared__ float sa[256], sb[256];
    float sum = 0.f, sq = 0.f;
    for (int j = tid; j < NE; j += 256) { float v = e[j]; sum += v; sq += v*v; }
    sa[tid] = sum; sb[tid] = sq; __syncthreads();
    for (int o = 128; o > 0; o >>= 1) {
        if (tid < o) { sa[tid] += sa[tid+o]; sb[tid] += sb[tid+o]; }
        __syncthreads();
    }
    __shared__ float s_m, s_r;
    if (tid == 0) {
        float m = sa[0] / NE;
        float var = sb[0] / NE - m*m;
        s_m = m; s_r = rsqrtf(var + 1e-5f);
    }
    __syncthreads();
    float m = s_m, r = s_r;
    float* xo = g_X + (size_t)tok * NE;
    for (int j = tid; j < NE; j += 256) {
        float v = e[j];
        xo[j] = (v - m) * r * g[j] + bb[j];
    }
}

// ---------------- big GEMM (f32x2): C[M,N]=A[M,K]@W[K,N]+bias ----------------
// 64x128 tile, 256 threads, thread -> 4 row-pairs x 4 cols (f32x2 accumulators).
__global__ void k_gemm_n128(const float* __restrict__ A, const float* __restrict__ W,
                            const float* __restrict__ bias, float* __restrict__ C,
                            int K, int N, int remap) {
    __shared__ __align__(16) float As[32][68];
    __shared__ float Ws[32][132];
    int tid = threadIdx.x;
    int tx = tid & 31, ty = tid >> 5;
    int n0 = blockIdx.x * 128;
    int m0 = blockIdx.y * 64;
    const float* Ab = A + (size_t)m0 * K;

    unsigned long long acc[4][4];
    #pragma unroll
    for (int j = 0; j < 4; j++)
        #pragma unroll
        for (int c = 0; c < 4; c++) acc[j][c] = 0ull;

    for (int k0 = 0; k0 < K; k0 += 32) {
        #pragma unroll
        for (int i = 0; i < 8; i++) {
            int r = ty + i*8;
            As[tx][r] = Ab[(size_t)r*K + k0 + tx];
        }
        #pragma unroll
        for (int i = 0; i < 4; i++) {
            int kk = ty*4 + i;
            #pragma unroll
            for (int jj = 0; jj < 4; jj++)
                Ws[kk][tx + 32*jj] = W[(size_t)(k0 + kk)*N + n0 + tx + 32*jj];
        }
        __syncthreads();
        #pragma unroll
        for (int k = 0; k < 32; k++) {
            ulonglong2 aA = *reinterpret_cast<const ulonglong2*>(&As[k][ty*8]);
            ulonglong2 aB = *reinterpret_cast<const ulonglong2*>(&As[k][ty*8 + 4]);
            unsigned long long w[4];
            #pragma unroll
            for (int c = 0; c < 4; c++) w[c] = pk2(Ws[k][tx + 32*c]);
            #pragma unroll
            for (int c = 0; c < 4; c++) {
                acc[0][c] = fma2(aA.x, w[c], acc[0][c]);
                acc[1][c] = fma2(aA.y, w[c], acc[1][c]);
                acc[2][c] = fma2(aB.x, w[c], acc[2][c]);
                acc[3][c] = fma2(aB.y, w[c], acc[3][c]);
            }
        }
        __syncthreads();
    }
    float bv[4];
    #pragma unroll
    for (int c = 0; c < 4; c++) bv[c] = bias ? bias[n0 + tx + 32*c] : 0.f;
    #pragma unroll
    for (int j = 0; j < 4; j++) {
        int ga = m0 + ty*8 + 2*j, gb = ga + 1;
        size_t ra = remap ? (size_t)((ga & 63)*64 + (ga >> 6)) : (size_t)ga;
        size_t rb = remap ? (size_t)((gb & 63)*64 + (gb >> 6)) : (size_t)gb;
        #pragma unroll
        for (int c = 0; c < 4; c++) {
            float lo, hi;
            unpk(acc[j][c], lo, hi);
            C[ra*N + n0 + tx + 32*c] = lo + bv[c];
            C[rb*N + n0 + tx + 32*c] = hi + bv[c];
        }
    }
}

// ================= persistent recurrence kernel ==============================

__device__ __forceinline__ void gridbar() {
    __syncthreads();
    if (threadIdx.x == 0) {
        __threadfence();
        unsigned g = g_gen;
        if (atomicAdd(&g_bar, 1u) == GRID - 1) {
            g_bar = 0;
            __threadfence();
            g_gen = g + 1;
        } else {
            while (g_gen == g) { __nanosleep(64); }
        }
        __threadfence();
    }
    __syncthreads();
}

// 64x16-col tile GEMM, K split across FOUR 64-thread quarters, 2 cols/thread,
// f32x2 + cp.async double buffering (16-k chunks).
// AT: transposed A [K][64]. C tile at col n0 (+bias)(+Add).
// Emits per-row (sum,sumsq) partials into pst[row*64].
// sm layout (floats): [0,8192) A: quarter q at q*2048, 2 bufs x 1024.
//                     [8192,10240) W: quarter q at 8192+q*512, 2 bufs x 256.
// Epilogue: quarter q's 64x16 partial aliased into sm[q*2048 .. q*2048+1024).
__device__ __forceinline__ void gemm16(
    const float* __restrict__ AT, int K,
    const float* __restrict__ W, int N, int n0,
    const float* __restrict__ bias, const float* __restrict__ Add,
    float* __restrict__ C, float2* __restrict__ pst,
    float* __restrict__ sm)
{
    int tid = threadIdx.x;
    int qr = tid >> 6;                   // K-quarter 0..3
    int lt = tid & 63;
    int q  = lt >> 3;                    // rowgroup 0..7 (8 rows)
    int cp = lt & 7;                     // colpair 0..7 (cols cp*2, cp*2+1)
    int Kq = K >> 2;
    int nc = Kq >> 4;                    // chunks of 16 k
    const float* ATq = AT + (size_t)qr * Kq * 64;
    const float* Wq  = W  + (size_t)qr * Kq * N;
    float* Abase = sm + qr * 2048;
    float* Wbase = sm + 8192 + qr * 512;
    unsigned smA = (unsigned)__cvta_generic_to_shared(Abase);
    unsigned smW = (unsigned)__cvta_generic_to_shared(Wbase);

    unsigned long long acc[8];           // [0..3]: col cp*2 rows, [4..7]: col cp*2+1
    #pragma unroll
    for (int i = 0; i < 8; i++) acc[i] = 0ull;

    // prefetch chunk 0 of this quarter: A 1024 floats (4x16B/thr), W 256 (1x16B/thr)
    #pragma unroll
    for (int ii = 0; ii < 4; ii++)
        cpa16(smA + (lt + 64*ii)*16, ATq + (size_t)(lt + 64*ii)*4);
    cpa16(smW + lt*16, Wq + (size_t)(lt >> 2)*N + n0 + (lt & 3)*4);
    asm volatile("cp.async.commit_group;");

    for (int ch = 0; ch < nc; ch++) {
        if (ch + 1 < nc) {
            int k0 = (ch + 1) << 4;
            int bs = (ch + 1) & 1;
            const float* aseg = ATq + (size_t)k0 * 64;
            #pragma unroll
            for (int ii = 0; ii < 4; ii++)
                cpa16(smA + bs*4096 + (lt + 64*ii)*16, aseg + (size_t)(lt + 64*ii)*4);
            cpa16(smW + bs*1024 + lt*16,
                  Wq + (size_t)(k0 + (lt >> 2))*N + n0 + (lt & 3)*4);
            asm volatile("cp.async.commit_group;");
            asm volatile("cp.async.wait_group 1;");
        } else {
            asm volatile("cp.async.wait_group 0;");
        }
        asm volatile("bar.sync %0, 64;" :: "r"(qr + 1) : "memory");
        const float* As  = Abase + (ch & 1)*1024;
        const float* Wsb = Wbase + (ch & 1)*256;
        #pragma unroll
        for (int k = 0; k < 16; k++) {
            ulonglong2 aA = *reinterpret_cast<const ulonglong2*>(As + k*64 + q*8);
            ulonglong2 aB = *reinterpret_cast<const ulonglong2*>(As + k*64 + q*8 + 4);
            float2 wv = *reinterpret_cast<const float2*>(Wsb + k*16 + cp*2);
            unsigned long long w0 = pk2(wv.x);
            unsigned long long w1 = pk2(wv.y);
            acc[0] = fma2(aA.x, w0, acc[0]);
            acc[1] = fma2(aA.y, w0, acc[1]);
            acc[2] = fma2(aB.x, w0, acc[2]);
            acc[3] = fma2(aB.y, w0, acc[3]);
            acc[4] = fma2(aA.x, w1, acc[4]);
            acc[5] = fma2(aA.y, w1, acc[5]);
            acc[6] = fma2(aB.x, w1, acc[6]);
            acc[7] = fma2(aB.y, w1, acc[7]);
        }
        asm volatile("bar.sync %0, 64;" :: "r"(qr + 1) : "memory");
    }

    // dump this quarter's 64x16 partial into its own (now dead) A region
    {
        float o[2][8];
        unpk(acc[0], o[0][0], o[0][1]);
        unpk(acc[1], o[0][2], o[0][3]);
        unpk(acc[2], o[0][4], o[0][5]);
        unpk(acc[3], o[0][6], o[0][7]);
        unpk(acc[4], o[1][0], o[1][1]);
        unpk(acc[5], o[1][2], o[1][3]);
        unpk(acc[6], o[1][4], o[1][5]);
        unpk(acc[7], o[1][6], o[1][7]);
        #pragma unroll
        for (int c = 0; c < 2; c++)
            #pragma unroll
            for (int i = 0; i < 8; i++)
                Abase[(q*8 + i)*16 + cp*2 + c] = o[c][i];
    }
    __syncthreads();

    // all 256 threads finish 4 rows each: sum 4 quarters, bias/Add, store, stats
    {
        int c2 = tid & 15, q4 = tid >> 4;   // rows q4*4..q4*4+3
        float bv = bias ? bias[n0 + c2] : 0.f;
        #pragma unroll
        for (int i = 0; i < 4; i++) {
            int r = q4*4 + i;
            float v = sm[r*16 + c2] + sm[2048 + r*16 + c2]
                    + sm[4096 + r*16 + c2] + sm[6144 + r*16 + c2] + bv;
            if (Add) v += Add[(size_t)r*N + n0 + c2];
            C[(size_t)r*N + n0 + c2] = v;
            float s = v, qq = v*v;
            #pragma unroll
            for (int m = 1; m < 16; m <<= 1) {
                s  += __shfl_xor_sync(0xffffffffu, s,  m);
                qq += __shfl_xor_sync(0xffffffffu, qq, m);
            }
            if (c2 == 0) pst[r*64] = make_float2(s, qq);
        }
    }
    __syncthreads();
}

// warp-cooperative stats finalize: sum T partials, return (mean, rstd)
__device__ __forceinline__ float2 warp_stat(const float2* __restrict__ p, int T, float inv_hid) {
    int l = threadIdx.x & 31;
    float s = p[l].x, q = p[l].y;
    if (l + 32 < T) { s += p[l+32].x; q += p[l+32].y; }
    #pragma unroll
    for (int o = 16; o > 0; o >>= 1) {
        s += __shfl_xor_sync(0xffffffffu, s, o);
        q += __shfl_xor_sync(0xffffffffu, q, o);
    }
    float m = s * inv_hid;
    float r = rsqrtf(q * inv_hid - m*m + 1e-5f);
    return make_float2(m, r);
}

__device__ __forceinline__ float sigm(float x) { return 1.f / (1.f + expf(-x)); }

__global__ void __launch_bounds__(TPB, 2) k_recur(
    const float* __restrict__ lWi, const float* __restrict__ lbh,
    const float* __restrict__ lWh,
    const float* __restrict__ llig, const float* __restrict__ llib,
    const float* __restrict__ llhg, const float* __restrict__ llhb,
    const float* __restrict__ hWi,  const float* __restrict__ hbi,
    const float* __restrict__ hWh,  const float* __restrict__ hbh,
    const float* __restrict__ hlig, const float* __restrict__ hlib,
    const float* __restrict__ hlhg, const float* __restrict__ hlhb)
{
    __shared__ __align__(16) float sm[10240];
    __shared__ float s_st[12];

    const float* lWi_h = lWi + (size_t)NE * 3 * NH;  // rows 768..1535 of low_Wi
    int bid = blockIdx.x, tid = threadIdx.x;
    int w = tid >> 5;
    int b = bid & 63, third = bid >> 6;

    for (int t = 0; t < NS; t++) {
        const float* ixt = g_IX + (size_t)t * NB * 3 * NH;
        for (int c = 0; c < 3; c++) {
            // ---- phase A: HG(u=0) + ILOW (both depend only on current state)
            gemm16(g_hlT, NH, lWh, 3*NH, bid*16, lbh, nullptr,
                   g_HG, g_psB + (bid>>6)*4096 + (bid & 63), sm);
            gemm16(g_hhT, NHH, lWi_h, 3*NH, bid*16, nullptr, ixt,
                   g_ILraw, g_psA + (bid>>6)*4096 + (bid & 63), sm);
            gridbar();

            // ---- low-cell inner loop ----------------------------------------
            for (int u = 0; u < 5; u++) {
                // combine: LN(IL) + LN(HG) + gates -> h_lT
                for (int s = w; s < 6; s += 8) {
                    const float2* p = (s < 3)
                        ? g_psA + s*4096 + b*64
                        : g_psB + (s-3)*4096 + b*64;
                    float2 mr = warp_stat(p, 64, 1.f/NH);
                    if ((tid & 31) == 0) { s_st[2*s] = mr.x; s_st[2*s+1] = mr.y; }
                }
                __syncthreads();
                {
                    const float* Ib = g_ILraw + (size_t)b*3*NH;
                    const float* Hb = g_HG    + (size_t)b*3*NH;
                    int js = (third * NH) / 3, je = ((third + 1) * NH) / 3;
                    for (int j = js + tid; j < je; j += TPB) {
                        float i0 = (Ib[j       ] - s_st[0])*s_st[1]*llig[j       ] + llib[j       ];
                        float i1 = (Ib[NH  + j ] - s_st[2])*s_st[3]*llig[NH  + j ] + llib[NH  + j ];
                        float i2 = (Ib[2*NH + j] - s_st[4])*s_st[5]*llig[2*NH + j] + llib[2*NH + j];
                        float h0 = (Hb[j       ] - s_st[6])*s_st[7]*llhg[j       ] + llhb[j       ];
                        float h1 = (Hb[NH  + j ] - s_st[8])*s_st[9]*llhg[NH  + j ] + llhb[NH  + j ];
                        float h2 = (Hb[2*NH + j] - s_st[10])*s_st[11]*llhg[2*NH + j] + llhb[2*NH + j];
                        float r = sigm(i0 + h0);
                        float z = sigm(i1 + h1);
                        float n = tanhf(i2 + r*h2);
                        float hp = g_hlT[(size_t)j*64 + b];
                        g_hlT[(size_t)j*64 + b] = (1.f - z)*n + z*hp;
                    }
                }
                gridbar();
                if (u < 4) {
                    gemm16(g_hlT, NH, lWh, 3*NH, bid*16, lbh, nullptr,
                           g_HG, g_psB + (bid>>6)*4096 + (bid & 63), sm);
                    gridbar();
                }
            }

            // ---- high-cell GEMMs (288 tile jobs over 192 blocks) ------------
            for (int job = bid; job < 288; job += GRID) {
                if (job < 144) {
                    gemm16(g_hlT, NH, hWi, 3*NHH, job*16, hbi, nullptr,
                           g_IHI, g_psA + (job/48)*4096 + (job%48), sm);
                } else {
                    int nt = job - 144;
                    gemm16(g_hhT, NHH, hWh, 3*NHH, nt*16, hbh, nullptr,
                           g_HHG, g_psB + (nt/48)*4096 + (nt%48), sm);
                }
            }
            gridbar();

            // ---- high combine -> h_hT (+history at c==2) --------------------
            for (int s = w; s < 6; s += 8) {
                const float2* p = (s < 3)
                    ? g_psA + s*4096 + b*64
                    : g_psB + (s-3)*4096 + b*64;
                float2 mr = warp_stat(p, 48, 1.f/NHH);
                if ((tid & 31) == 0) { s_st[2*s] = mr.x; s_st[2*s+1] = mr.y; }
            }
            __syncthreads();
            {
                const float* Ib = g_IHI + (size_t)b*3*NHH;
                const float* Hb = g_HHG + (size_t)b*3*NHH;
                for (int j = third*256 + tid; j < third*256 + 256; j += TPB) {
                    float i0 = (Ib[j        ] - s_st[0])*s_st[1]*hlig[j        ] + hlib[j        ];
                    float i1 = (Ib[NHH  + j ] - s_st[2])*s_st[3]*hlig[NHH  + j ] + hlib[NHH  + j ];
                    float i2 = (Ib[2*NHH + j] - s_st[4])*s_st[5]*hlig[2*NHH + j] + hlib[2*NHH + j];
                    float h0 = (Hb[j        ] - s_st[6])*s_st[7]*hlhg[j        ] + hlhb[j        ];
                    float h1 = (Hb[NHH  + j ] - s_st[8])*s_st[9]*hlhg[NHH  + j ] + hlhb[NHH  + j ];
                    float h2 = (Hb[2*NHH + j] - s_st[10])*s_st[11]*hlhg[2*NHH + j] + hlhb[2*NHH + j];
                    float r = sigm(i0 + h0);
                    float z = sigm(i1 + h1);
                    float n = tanhf(i2 + r*h2);
                    float hp = g_hhT[(size_t)j*64 + b];
                    float nv = (1.f - z)*n + z*hp;
                    g_hhT[(size_t)j*64 + b] = nv;
                    if (c == 2) g_HH[(size_t)(t*64 + b)*NHH + j] = nv;
                }
            }
            gridbar();
        }
    }
}

// ---------------- host orchestration ----------------------------------------
extern "C" void kernel_launch(void* const* d_in, const int* in_sizes, int n_in,
                              void* d_out, int out_size) {
    const int*   ids  = (const int*)  d_in[0];
    const float* emb  = (const float*)d_in[1];
    const float* leg  = (const float*)d_in[2];
    const float* leb  = (const float*)d_in[3];
    const float* lWi  = (const float*)d_in[4];   // [1536, 3072]
    const float* lbi  = (const float*)d_in[5];
    const float* lWh  = (const float*)d_in[6];   // [1024, 3072]
    const float* lbh  = (const float*)d_in[7];
    const float* llig = (const float*)d_in[8];
    const float* llib = (const float*)d_in[9];
    const float* llhg = (const float*)d_in[10];
    const float* llhb = (const float*)d_in[11];
    const float* hWi  = (const float*)d_in[12];  // [1024, 2304]
    const float* hbi  = (const float*)d_in[13];
    const float* hWh  = (const float*)d_in[14];  // [768, 2304]
    const float* hbh  = (const float*)d_in[15];
    const float* hlig = (const float*)d_in[16];
    const float* hlib = (const float*)d_in[17];
    const float* hlhg = (const float*)d_in[18];
    const float* hlhb = (const float*)d_in[19];
    const float* Wout = (const float*)d_in[20];  // [768, 32000]
    const float* bout = (const float*)d_in[21];
    float* out = (float*)d_out;

    float *pX, *pIX, *pHH;
    cudaGetSymbolAddress((void**)&pX,  g_X);
    cudaGetSymbolAddress((void**)&pIX, g_IX);
    cudaGetSymbolAddress((void**)&pHH, g_HH);

    // zero hidden states (transposed layouts)
    k_init<<<256, 256>>>();

    // x = LN(emb[ids]) laid out [S, B, E]
    k_embed<<<NB*NS, 256>>>(ids, emb, leg, leb);

    // IX = x @ Wi_x + bi for ALL tokens up front (reused 15x per step)
    k_gemm_n128<<<dim3((3*NH)/128, (NB*NS)/64), 256>>>(pX, lWi, lbi, pIX, NE, 3*NH, 0);

    // full recurrence in ONE persistent kernel (software grid barriers)
    k_recur<<<GRID, TPB>>>(lWi, lbh, lWh,
                           llig, llib, llhg, llhb,
                           hWi, hbi, hWh, hbh,
                           hlig, hlib, hlhg, hlhb);

    // logits = h_h_hist @ Wout + bout, row remap (s*64+b) -> out[(b*64+s)*V]
    k_gemm_n128<<<dim3(NV/128, (NB*NS)/64), 256>>>(pHH, Wout, bout, out, NHH, NV, 1);
}

// round 11
// speedup vs baseline: 2.0647x; 1.1008x over previous
#include <cuda_runtime.h>
#include <math.h>
#include <stdint.h>

// Problem dims
#define NB 64
#define NS 64
#define NV 32000
#define NE 768
#define NH 1024
#define NHH 768

#define GRID 128
#define TPB  256

typedef unsigned long long ull;

// ---------------- scratch (device globals; no allocations allowed) ----------
__device__ float g_X    [NB*NS*NE];            // LN'd embeddings, row = s*64+b
__device__ float g_IX   [(size_t)NB*NS*3*NH];  // x_t @ Wi_x + bi, per token
__device__ float g_ILraw[NB*3*NH];             // raw ILOW = IX_t + h_h @ Wi_h
__device__ float g_HG   [NB*3*NH];             // raw h_l @ Wh + bh
__device__ float g_IHI  [NB*3*NHH];            // raw h_l @ hWi + hbi
__device__ float g_HHG  [NB*3*NHH];            // raw h_h @ hWh + hbh
__device__ float2 g_psA [3*64*128];            // partial (sum,sumsq) stats
__device__ float2 g_psB [3*64*128];
__device__ float g_hlT  [NH*64];               // h_l transposed [j][b]
__device__ float g_hhT  [NHH*64];              // h_h transposed [j][b]
__device__ float g_HH   [NB*NS*NHH];           // h_h history, row = t*64+b

// grid barrier state (self-resetting; generation is monotonic across replays)
__device__ unsigned g_bar = 0;
__device__ volatile unsigned g_gen = 0;

// ---------------- f32x2 helpers ---------------------------------------------
__device__ __forceinline__ ull fma2(ull a, ull b, ull c) {
    ull d;
    asm("fma.rn.f32x2 %0, %1, %2, %3;" : "=l"(d) : "l"(a), "l"(b), "l"(c));
    return d;
}
__device__ __forceinline__ ull pk2(float x) {
    ull d;
    asm("mov.b64 %0, {%1, %1};" : "=l"(d) : "f"(x));
    return d;
}
__device__ __forceinline__ void unpk(ull v, float& lo, float& hi) {
    asm("mov.b64 {%0, %1}, %2;" : "=f"(lo), "=f"(hi) : "l"(v));
}
__device__ __forceinline__ void cpa16(unsigned dst, const void* src) {
    asm volatile("cp.async.cg.shared.global [%0], [%1], 16;" :: "r"(dst), "l"(src));
}

// ---------------- init: zero hidden states (transposed layouts) -------------
__global__ void k_init() {
    int i = blockIdx.x * 256 + threadIdx.x;
    if (i < NH*64)  g_hlT[i] = 0.f;
    if (i < NHH*64) g_hhT[i] = 0.f;
}

// ---------------- embedding lookup + LayerNorm ------------------------------
__global__ void k_embed(const int* __restrict__ ids, const float* __restrict__ emb,
                        const float* __restrict__ g, const float* __restrict__ bb) {
    int tok = blockIdx.x;            // tok = s*64 + b
    int b = tok & 63, s = tok >> 6;
    int id = ids[b*NS + s];
    const float* e = emb + (size_t)id * NE;
    int tid = threadIdx.x;

    __shared__ float sa[256], sb[256];
    float sum = 0.f, sq = 0.f;
    for (int j = tid; j < NE; j += 256) { float v = e[j]; sum += v; sq += v*v; }
    sa[tid] = sum; sb[tid] = sq; __syncthreads();
    for (int o = 128; o > 0; o >>= 1) {
        if (tid < o) { sa[tid] += sa[tid+o]; sb[tid] += sb[tid+o]; }
        __syncthreads();
    }
    __shared__ float s_m, s_r;
    if (tid == 0) {
        float m = sa[0] / NE;
        float var = sb[0] / NE - m*m;
        s_m = m; s_r = rsqrtf(var + 1e-5f);
    }
    __syncthreads();
    float m = s_m, r = s_r;
    float* xo = g_X + (size_t)tok * NE;
    for (int j = tid; j < NE; j += 256) {
        float v = e[j];
        xo[j] = (v - m) * r * g[j] + bb[j];
    }
}

// ---------------- big GEMM (f32x2): 128x128 tiles ----------------------------
// 256 threads, thread -> 8 rows x 8 cols. Optional output row remap.
__global__ void __launch_bounds__(256) k_gemm_big(
    const float* __restrict__ A, const float* __restrict__ W,
    const float* __restrict__ bias, float* __restrict__ C,
    int K, int N, int remap)
{
    __shared__ __align__(16) float As[32][136];
    __shared__ __align__(16) float Ws[32][136];
    int tid = threadIdx.x;
    int tx = tid & 31, ty = tid >> 5;    // load mapping
    int cx = tid & 15, ry = tid >> 4;    // compute: rows ry*8..+7, cols cx*8..+7
    int n0 = blockIdx.x * 128;
    int m0 = blockIdx.y * 128;

    ull acc[4][8];
    #pragma unroll
    for (int p = 0; p < 4; p++)
        #pragma unroll
        for (int c = 0; c < 8; c++) acc[p][c] = 0ull;

    for (int k0 = 0; k0 < K; k0 += 32) {
        #pragma unroll
        for (int i = 0; i < 16; i++)
            As[tx][ty + 8*i] = A[(size_t)(m0 + ty + 8*i)*K + k0 + tx];
        #pragma unroll
        for (int ii = 0; ii < 4; ii++) {
            int kk = ty*4 + ii;
            #pragma unroll
            for (int jj = 0; jj < 4; jj++)
                Ws[kk][tx + 32*jj] = W[(size_t)(k0 + kk)*N + n0 + tx + 32*jj];
        }
        __syncthreads();
        #pragma unroll
        for (int k = 0; k < 32; k++) {
            ulonglong2 a0 = *reinterpret_cast<const ulonglong2*>(&As[k][ry*8]);
            ulonglong2 a1 = *reinterpret_cast<const ulonglong2*>(&As[k][ry*8 + 4]);
            float4 w0 = *reinterpret_cast<const float4*>(&Ws[k][cx*8]);
            float4 w1 = *reinterpret_cast<const float4*>(&Ws[k][cx*8 + 4]);
            ull wp[8];
            wp[0] = pk2(w0.x); wp[1] = pk2(w0.y); wp[2] = pk2(w0.z); wp[3] = pk2(w0.w);
            wp[4] = pk2(w1.x); wp[5] = pk2(w1.y); wp[6] = pk2(w1.z); wp[7] = pk2(w1.w);
            #pragma unroll
            for (int c = 0; c < 8; c++) {
                acc[0][c] = fma2(a0.x, wp[c], acc[0][c]);
                acc[1][c] = fma2(a0.y, wp[c], acc[1][c]);
                acc[2][c] = fma2(a1.x, wp[c], acc[2][c]);
                acc[3][c] = fma2(a1.y, wp[c], acc[3][c]);
            }
        }
        __syncthreads();
    }
    float bv[8];
    #pragma unroll
    for (int c = 0; c < 8; c++) bv[c] = bias ? bias[n0 + cx*8 + c] : 0.f;
    #pragma unroll
    for (int p = 0; p < 4; p++) {
        int ga = m0 + ry*8 + 2*p, gb = ga + 1;
        size_t ra = remap ? (size_t)((ga & 63)*64 + (ga >> 6)) : (size_t)ga;
        size_t rb = remap ? (size_t)((gb & 63)*64 + (gb >> 6)) : (size_t)gb;
        float oa[8], ob[8];
        #pragma unroll
        for (int c = 0; c < 8; c++) {
            float lo, hi;
            unpk(acc[p][c], lo, hi);
            oa[c] = lo + bv[c];
            ob[c] = hi + bv[c];
        }
        float4* pa = reinterpret_cast<float4*>(C + ra*N + n0 + cx*8);
        float4* pb = reinterpret_cast<float4*>(C + rb*N + n0 + cx*8);
        pa[0] = make_float4(oa[0], oa[1], oa[2], oa[3]);
        pa[1] = make_float4(oa[4], oa[5], oa[6], oa[7]);
        pb[0] = make_float4(ob[0], ob[1], ob[2], ob[3]);
        pb[1] = make_float4(ob[4], ob[5], ob[6], ob[7]);
    }
}

// ================= persistent recurrence kernel ==============================

__device__ __forceinline__ void gridbar() {
    __syncthreads();
    if (threadIdx.x == 0) {
        __threadfence();
        unsigned g = g_gen;
        if (atomicAdd(&g_bar, 1u) == GRID - 1) {
            g_bar = 0;
            __threadfence();
            g_gen = g + 1;
        } else {
            while (g_gen == g) { __nanosleep(64); }
        }
        __threadfence();
    }
    __syncthreads();
}

// Gate-sliced GEMM: block computes cols [g*gw + col0, +8) for each gate g=0..2.
// K split across FOUR 64-thread quarters, f32x2, cp.async double buffering
// (16-k chunks). AT: transposed A [K][64]. Emits per-row/gate (sum,sumsq) of
// this 8-col slice into pst[gate*64*TC + row*TC] (pst pre-offset by tile id).
// sm (floats): [0,8192) A: quarter q at q*2048 (2 bufs x 1024);
//              [8192,11264) W: quarter q at 8192+q*768 (2 bufs x 384 = 16k x 24).
// Epilogue: quarter q's 64x24 partial aliased into its A region.
__device__ __forceinline__ void gemmG(
    const float* __restrict__ AT, int K,
    const float* __restrict__ W, int N, int gw, int col0,
    const float* __restrict__ bias, const float* __restrict__ Add,
    float* __restrict__ C, float2* __restrict__ pst, int TC,
    float* __restrict__ sm)
{
    int tid = threadIdx.x;
    int qr = tid >> 6;                   // K-quarter 0..3
    int lt = tid & 63;
    int rg = lt >> 3;                    // rowgroup 0..7 (rows rg*8..+7)
    int cc = lt & 7;                     // col within 8-wide gate slice
    int Kq = K >> 2;
    int nc = Kq >> 4;                    // 16-k chunks
    const float* ATq = AT + (size_t)qr * Kq * 64;
    float* Abase = sm + qr * 2048;
    float* Wbase = sm + 8192 + qr * 768;
    unsigned smA = (unsigned)__cvta_generic_to_shared(Abase);
    unsigned smW = (unsigned)__cvta_generic_to_shared(Wbase);

    // W transfer descriptors: 96 x 16B per chunk (16k x 3 gates x 2 halves)
    int t0 = lt, t1 = lt + 64;
    int k0w = t0 / 6, r0w = t0 - 6*k0w;  // gate=r>>1, half=r&1
    int k1w = t1 / 6, r1w = t1 - 6*k1w;
    const float* wsrc0 = W + (size_t)(qr*Kq + k0w)*N + (r0w >> 1)*gw + col0 + (r0w & 1)*4;
    const float* wsrc1 = W + (size_t)(qr*Kq + k1w)*N + (r1w >> 1)*gw + col0 + (r1w & 1)*4;
    unsigned wdst0 = smW + (unsigned)(k0w*24 + (r0w >> 1)*8 + (r0w & 1)*4)*4;
    unsigned wdst1 = smW + (unsigned)(k1w*24 + (r1w >> 1)*8 + (r1w & 1)*4)*4;

    ull acc[3][4];
    #pragma unroll
    for (int g = 0; g < 3; g++)
        #pragma unroll
        for (int j = 0; j < 4; j++) acc[g][j] = 0ull;

    // prefetch chunk 0
    #pragma unroll
    for (int ii = 0; ii < 4; ii++)
        cpa16(smA + (lt + 64*ii)*16, ATq + (size_t)(lt + 64*ii)*4);
    cpa16(wdst0, wsrc0);
    if (lt < 32) cpa16(wdst1, wsrc1);
    asm volatile("cp.async.commit_group;");

    for (int ch = 0; ch < nc; ch++) {
        if (ch + 1 < nc) {
            int bs = (ch + 1) & 1;
            const float* aseg = ATq + (size_t)(ch + 1) * 16 * 64;
            #pragma unroll
            for (int ii = 0; ii < 4; ii++)
                cpa16(smA + bs*4096 + (lt + 64*ii)*16, aseg + (size_t)(lt + 64*ii)*4);
            cpa16(wdst0 + bs*1536, wsrc0 + 16*N);
            if (lt < 32) cpa16(wdst1 + bs*1536, wsrc1 + 16*N);
            wsrc0 += 16*N; wsrc1 += 16*N;
            asm volatile("cp.async.commit_group;");
            asm volatile("cp.async.wait_group 1;");
        } else {
            asm volatile("cp.async.wait_group 0;");
        }
        asm volatile("bar.sync %0, 64;" :: "r"(qr + 1) : "memory");
        const float* As  = Abase + (ch & 1)*1024;
        const float* Wsb = Wbase + (ch & 1)*384;
        #pragma unroll
        for (int k = 0; k < 16; k++) {
            ulonglong2 aA = *reinterpret_cast<const ulonglong2*>(As + k*64 + rg*8);
            ulonglong2 aB = *reinterpret_cast<const ulonglong2*>(As + k*64 + rg*8 + 4);
            #pragma unroll
            for (int g = 0; g < 3; g++) {
                ull w = pk2(Wsb[k*24 + g*8 + cc]);
                acc[g][0] = fma2(aA.x, w, acc[g][0]);
                acc[g][1] = fma2(aA.y, w, acc[g][1]);
                acc[g][2] = fma2(aB.x, w, acc[g][2]);
                acc[g][3] = fma2(aB.y, w, acc[g][3]);
            }
        }
        asm volatile("bar.sync %0, 64;" :: "r"(qr + 1) : "memory");
    }

    // dump this quarter's 64x24 partial into its own (now dead) A region
    #pragma unroll
    for (int g = 0; g < 3; g++) {
        float o[8];
        unpk(acc[g][0], o[0], o[1]);
        unpk(acc[g][1], o[2], o[3]);
        unpk(acc[g][2], o[4], o[5]);
        unpk(acc[g][3], o[6], o[7]);
        #pragma unroll
        for (int i = 0; i < 8; i++)
            Abase[(rg*8 + i)*24 + g*8 + cc] = o[i];
    }
    __syncthreads();

    // epilogue: 192 threads, each handles one (gate,row): sum 4 quarters over
    // 8 cols, +bias/+Add, store, emit LN stats for this slice (no shuffles).
    if (tid < 192) {
        int gate = tid >> 6, row = tid & 63;
        int base = row*24 + gate*8;
        float4 v0 = make_float4(0.f, 0.f, 0.f, 0.f);
        float4 v1 = make_float4(0.f, 0.f, 0.f, 0.f);
        #pragma unroll
        for (int q = 0; q < 4; q++) {
            float4 p0 = *reinterpret_cast<const float4*>(sm + q*2048 + base);
            float4 p1 = *reinterpret_cast<const float4*>(sm + q*2048 + base + 4);
            v0.x += p0.x; v0.y += p0.y; v0.z += p0.z; v0.w += p0.w;
            v1.x += p1.x; v1.y += p1.y; v1.z += p1.z; v1.w += p1.w;
        }
        size_t cix = (size_t)gate*gw + col0;
        if (bias) {
            float4 b0 = *reinterpret_cast<const float4*>(bias + cix);
            float4 b1 = *reinterpret_cast<const float4*>(bias + cix + 4);
            v0.x += b0.x; v0.y += b0.y; v0.z += b0.z; v0.w += b0.w;
            v1.x += b1.x; v1.y += b1.y; v1.z += b1.z; v1.w += b1.w;
        }
        if (Add) {
            float4 a0 = *reinterpret_cast<const float4*>(Add + (size_t)row*N + cix);
            float4 a1 = *reinterpret_cast<const float4*>(Add + (size_t)row*N + cix + 4);
            v0.x += a0.x; v0.y += a0.y; v0.z += a0.z; v0.w += a0.w;
            v1.x += a1.x; v1.y += a1.y; v1.z += a1.z; v1.w += a1.w;
        }
        *reinterpret_cast<float4*>(C + (size_t)row*N + cix)     = v0;
        *reinterpret_cast<float4*>(C + (size_t)row*N + cix + 4) = v1;
        float s = v0.x + v0.y + v0.z + v0.w + v1.x + v1.y + v1.z + v1.w;
        float qq = v0.x*v0.x + v0.y*v0.y + v0.z*v0.z + v0.w*v0.w
                 + v1.x*v1.x + v1.y*v1.y + v1.z*v1.z + v1.w*v1.w;
        pst[(size_t)gate*64*TC + row*TC] = make_float2(s, qq);
    }
    __syncthreads();
}

// warp-cooperative stats finalize: sum TC partials, return (mean, rstd)
__device__ __forceinline__ float2 warp_stat(const float2* __restrict__ p, int TC, float inv_hid) {
    int l = threadIdx.x & 31;
    float s = 0.f, q = 0.f;
    #pragma unroll
    for (int i = 0; i < 4; i++) {
        if (l + 32*i < TC) { s += p[l + 32*i].x; q += p[l + 32*i].y; }
    }
    #pragma unroll
    for (int o = 16; o > 0; o >>= 1) {
        s += __shfl_xor_sync(0xffffffffu, s, o);
        q += __shfl_xor_sync(0xffffffffu, q, o);
    }
    float m = s * inv_hid;
    float r = rsqrtf(q * inv_hid - m*m + 1e-5f);
    return make_float2(m, r);
}

__device__ __forceinline__ float sigm(float x) { return 1.f / (1.f + expf(-x)); }

__global__ void __launch_bounds__(TPB, 1) k_recur(
    const float* __restrict__ lWi, const float* __restrict__ lbh,
    const float* __restrict__ lWh,
    const float* __restrict__ llig, const float* __restrict__ llib,
    const float* __restrict__ llhg, const float* __restrict__ llhb,
    const float* __restrict__ hWi,  const float* __restrict__ hbi,
    const float* __restrict__ hWh,  const float* __restrict__ hbh,
    const float* __restrict__ hlig, const float* __restrict__ hlib,
    const float* __restrict__ hlhg, const float* __restrict__ hlhb)
{
    __shared__ __align__(16) float sm[11264];
    __shared__ float s_st[12];

    const float* lWi_h = lWi + (size_t)NE * 3 * NH;  // rows 768..1535 of low_Wi
    int bid = blockIdx.x, tid = threadIdx.x;
    int w = tid >> 5;
    int b = bid & 63, half = bid >> 6;
    int col0 = bid * 8;

    for (int t = 0; t < NS; t++) {
        const float* ixt = g_IX + (size_t)t * NB * 3 * NH;
        for (int c = 0; c < 3; c++) {
            // ---- phase A: HG(u=0) + ILOW (both depend only on current state)
            gemmG(g_hlT, NH, lWh, 3*NH, NH, col0, lbh, nullptr,
                  g_HG, g_psB + bid, 128, sm);
            gemmG(g_hhT, NHH, lWi_h, 3*NH, NH, col0, nullptr, ixt,
                  g_ILraw, g_psA + bid, 128, sm);
            gridbar();

            // ---- low-cell inner loop ----------------------------------------
            for (int u = 0; u < 5; u++) {
                // combine: LN(IL) + LN(HG) + gates -> h_lT
                if (w < 6) {
                    const float2* p = (w < 3)
                        ? g_psA + (size_t)w*64*128 + b*128
                        : g_psB + (size_t)(w-3)*64*128 + b*128;
                    float2 mr = warp_stat(p, 128, 1.f/NH);
                    if ((tid & 31) == 0) { s_st[2*w] = mr.x; s_st[2*w+1] = mr.y; }
                }
                __syncthreads();
                {
                    const float* Ib = g_ILraw + (size_t)b*3*NH;
                    const float* Hb = g_HG    + (size_t)b*3*NH;
                    int js = half * 512, je = js + 512;
                    for (int j = js + tid; j < je; j += TPB) {
                        float i0 = (Ib[j       ] - s_st[0])*s_st[1]*llig[j       ] + llib[j       ];
                        float i1 = (Ib[NH  + j ] - s_st[2])*s_st[3]*llig[NH  + j ] + llib[NH  + j ];
                        float i2 = (Ib[2*NH + j] - s_st[4])*s_st[5]*llig[2*NH + j] + llib[2*NH + j];
                        float h0 = (Hb[j       ] - s_st[6])*s_st[7]*llhg[j       ] + llhb[j       ];
                        float h1 = (Hb[NH  + j ] - s_st[8])*s_st[9]*llhg[NH  + j ] + llhb[NH  + j ];
                        float h2 = (Hb[2*NH + j] - s_st[10])*s_st[11]*llhg[2*NH + j] + llhb[2*NH + j];
                        float r = sigm(i0 + h0);
                        float z = sigm(i1 + h1);
                        float n = tanhf(i2 + r*h2);
                        float hp = g_hlT[(size_t)j*64 + b];
                        g_hlT[(size_t)j*64 + b] = (1.f - z)*n + z*hp;
                    }
                }
                gridbar();
                if (u < 4) {
                    gemmG(g_hlT, NH, lWh, 3*NH, NH, col0, lbh, nullptr,
                          g_HG, g_psB + bid, 128, sm);
                    gridbar();
                }
            }

            // ---- high-cell GEMMs: 96 blocks, 8-col gate slices --------------
            if (bid < 96) {
                gemmG(g_hlT, NH, hWi, 3*NHH, NHH, col0, hbi, nullptr,
                      g_IHI, g_psA + bid, 96, sm);
                gemmG(g_hhT, NHH, hWh, 3*NHH, NHH, col0, hbh, nullptr,
                      g_HHG, g_psB + bid, 96, sm);
            }
            gridbar();

            // ---- high combine -> h_hT (+history at c==2) --------------------
            if (w < 6) {
                const float2* p = (w < 3)
                    ? g_psA + (size_t)w*64*96 + b*96
                    : g_psB + (size_t)(w-3)*64*96 + b*96;
                float2 mr = warp_stat(p, 96, 1.f/NHH);
                if ((tid & 31) == 0) { s_st[2*w] = mr.x; s_st[2*w+1] = mr.y; }
            }
            __syncthreads();
            {
                const float* Ib = g_IHI + (size_t)b*3*NHH;
                const float* Hb = g_HHG + (size_t)b*3*NHH;
                int js = half * 384, je = js + 384;
                for (int j = js + tid; j < je; j += TPB) {
                    float i0 = (Ib[j        ] - s_st[0])*s_st[1]*hlig[j        ] + hlib[j        ];
                    float i1 = (Ib[NHH  + j ] - s_st[2])*s_st[3]*hlig[NHH  + j ] + hlib[NHH  + j ];
                    float i2 = (Ib[2*NHH + j] - s_st[4])*s_st[5]*hlig[2*NHH + j] + hlib[2*NHH + j];
                    float h0 = (Hb[j        ] - s_st[6])*s_st[7]*hlhg[j        ] + hlhb[j        ];
                    float h1 = (Hb[NHH  + j ] - s_st[8])*s_st[9]*hlhg[NHH  + j ] + hlhb[NHH  + j ];
                    float h2 = (Hb[2*NHH + j] - s_st[10])*s_st[11]*hlhg[2*NHH + j] + hlhb[2*NHH + j];
                    float r = sigm(i0 + h0);
                    float z = sigm(i1 + h1);
                    float n = tanhf(i2 + r*h2);
                    float hp = g_hhT[(size_t)j*64 + b];
                    float nv = (1.f - z)*n + z*hp;
                    g_hhT[(size_t)j*64 + b] = nv;
                    if (c == 2) g_HH[(size_t)(t*64 + b)*NHH + j] = nv;
                }
            }
            gridbar();
        }
    }
}

// ---------------- host orchestration ----------------------------------------
extern "C" void kernel_launch(void* const* d_in, const int* in_sizes, int n_in,
                              void* d_out, int out_size) {
    const int*   ids  = (const int*)  d_in[0];
    const float* emb  = (const float*)d_in[1];
    const float* leg  = (const float*)d_in[2];
    const float* leb  = (const float*)d_in[3];
    const float* lWi  = (const float*)d_in[4];   // [1536, 3072]
    const float* lbi  = (const float*)d_in[5];
    const float* lWh  = (const float*)d_in[6];   // [1024, 3072]
    const float* lbh  = (const float*)d_in[7];
    const float* llig = (const float*)d_in[8];
    const float* llib = (const float*)d_in[9];
    const float* llhg = (const float*)d_in[10];
    const float* llhb = (const float*)d_in[11];
    const float* hWi  = (const float*)d_in[12];  // [1024, 2304]
    const float* hbi  = (const float*)d_in[13];
    const float* hWh  = (const float*)d_in[14];  // [768, 2304]
    const float* hbh  = (const float*)d_in[15];
    const float* hlig = (const float*)d_in[16];
    const float* hlib = (const float*)d_in[17];
    const float* hlhg = (const float*)d_in[18];
    const float* hlhb = (const float*)d_in[19];
    const float* Wout = (const float*)d_in[20];  // [768, 32000]
    const float* bout = (const float*)d_in[21];
    float* out = (float*)d_out;

    float *pX, *pIX, *pHH;
    cudaGetSymbolAddress((void**)&pX,  g_X);
    cudaGetSymbolAddress((void**)&pIX, g_IX);
    cudaGetSymbolAddress((void**)&pHH, g_HH);

    // zero hidden states (transposed layouts)
    k_init<<<256, 256>>>();

    // x = LN(emb[ids]) laid out [S, B, E]
    k_embed<<<NB*NS, 256>>>(ids, emb, leg, leb);

    // IX = x @ Wi_x + bi for ALL tokens up front (reused 15x per step)
    k_gemm_big<<<dim3((3*NH)/128, (NB*NS)/128), 256>>>(pX, lWi, lbi, pIX, NE, 3*NH, 0);

    // full recurrence in ONE persistent kernel (software grid barriers)
    k_recur<<<GRID, TPB>>>(lWi, lbh, lWh,
                           llig, llib, llhg, llhb,
                           hWi, hbi, hWh, hbh,
                           hlig, hlib, hlhg, hlhb);

    // logits = h_h_hist @ Wout + bout, row remap (s*64+b) -> out[(b*64+s)*V]
    k_gemm_big<<<dim3(NV/128, (NB*NS)/128), 256>>>(pHH, Wout, bout, out, NHH, NV, 1);
}

// round 12
// speedup vs baseline: 2.1554x; 1.0439x over previous
#include <cuda_runtime.h>
#include <math.h>
#include <stdint.h>

// Problem dims
#define NB 64
#define NS 64
#define NV 32000
#define NE 768
#define NH 1024
#define NHH 768

#define GRID 128
#define TPB  512

typedef unsigned long long ull;

// ---------------- scratch (device globals; no allocations allowed) ----------
__device__ float g_X    [NB*NS*NE];            // LN'd embeddings, row = s*64+b
__device__ float g_IX   [(size_t)NB*NS*3*NH];  // x_t @ Wi_x + bi, per token
__device__ float g_ILraw[NB*3*NH];             // raw ILOW = IX_t + h_h @ Wi_h
__device__ float g_HG   [NB*3*NH];             // raw h_l @ Wh + bh
__device__ float g_IHI  [NB*3*NHH];            // raw h_l @ hWi + hbi
__device__ float g_HHG  [NB*3*NHH];            // raw h_h @ hWh + hbh
__device__ float2 g_psA [3*64*128];            // partial (sum,sumsq) stats
__device__ float2 g_psB [3*64*128];
__device__ float g_hlT  [NH*64];               // h_l transposed [j][b]
__device__ float g_hhT  [NHH*64];              // h_h transposed [j][b]
__device__ float g_HH   [NB*NS*NHH];           // h_h history, row = t*64+b

// grid barrier state (self-resetting; generation is monotonic across replays)
__device__ unsigned g_bar = 0;
__device__ volatile unsigned g_gen = 0;

// ---------------- f32x2 helpers ---------------------------------------------
__device__ __forceinline__ ull fma2(ull a, ull b, ull c) {
    ull d;
    asm("fma.rn.f32x2 %0, %1, %2, %3;" : "=l"(d) : "l"(a), "l"(b), "l"(c));
    return d;
}
__device__ __forceinline__ ull pk2(float x) {
    ull d;
    asm("mov.b64 %0, {%1, %1};" : "=l"(d) : "f"(x));
    return d;
}
__device__ __forceinline__ void unpk(ull v, float& lo, float& hi) {
    asm("mov.b64 {%0, %1}, %2;" : "=f"(lo), "=f"(hi) : "l"(v));
}
__device__ __forceinline__ void cpa16(unsigned dst, const void* src) {
    asm volatile("cp.async.cg.shared.global [%0], [%1], 16;" :: "r"(dst), "l"(src));
}

// ---------------- init: zero hidden states (transposed layouts) -------------
__global__ void k_init() {
    int i = blockIdx.x * 256 + threadIdx.x;
    if (i < NH*64)  g_hlT[i] = 0.f;
    if (i < NHH*64) g_hhT[i] = 0.f;
}

// ---------------- embedding lookup + LayerNorm ------------------------------
__global__ void k_embed(const int* __restrict__ ids, const float* __restrict__ emb,
                        const float* __restrict__ g, const float* __restrict__ bb) {
    int tok = blockIdx.x;            // tok = s*64 + b
    int b = tok & 63, s = tok >> 6;
    int id = ids[b*NS + s];
    const float* e = emb + (size_t)id * NE;
    int tid = threadIdx.x;

    __shared__ float sa[256], sb[256];
    float sum = 0.f, sq = 0.f;
    for (int j = tid; j < NE; j += 256) { float v = e[j]; sum += v; sq += v*v; }
    sa[tid] = sum; sb[tid] = sq; __syncthreads();
    for (int o = 128; o > 0; o >>= 1) {
        if (tid < o) { sa[tid] += sa[tid+o]; sb[tid] += sb[tid+o]; }
        __syncthreads();
    }
    __shared__ float s_m, s_r;
    if (tid == 0) {
        float m = sa[0] / NE;
        float var = sb[0] / NE - m*m;
        s_m = m; s_r = rsqrtf(var + 1e-5f);
    }
    __syncthreads();
    float m = s_m, r = s_r;
    float* xo = g_X + (size_t)tok * NE;
    for (int j = tid; j < NE; j += 256) {
        float v = e[j];
        xo[j] = (v - m) * r * g[j] + bb[j];
    }
}

// ---------------- big GEMM (f32x2): 128x128 tiles ----------------------------
// 256 threads, thread -> 8 rows x 8 cols. Optional output row remap.
__global__ void __launch_bounds__(256) k_gemm_big(
    const float* __restrict__ A, const float* __restrict__ W,
    const float* __restrict__ bias, float* __restrict__ C,
    int K, int N, int remap)
{
    __shared__ __align__(16) float As[32][136];
    __shared__ __align__(16) float Ws[32][136];
    int tid = threadIdx.x;
    int tx = tid & 31, ty = tid >> 5;    // load mapping
    int cx = tid & 15, ry = tid >> 4;    // compute: rows ry*8..+7, cols cx*8..+7
    int n0 = blockIdx.x * 128;
    int m0 = blockIdx.y * 128;

    ull acc[4][8];
    #pragma unroll
    for (int p = 0; p < 4; p++)
        #pragma unroll
        for (int c = 0; c < 8; c++) acc[p][c] = 0ull;

    for (int k0 = 0; k0 < K; k0 += 32) {
        #pragma unroll
        for (int i = 0; i < 16; i++)
            As[tx][ty + 8*i] = A[(size_t)(m0 + ty + 8*i)*K + k0 + tx];
        #pragma unroll
        for (int ii = 0; ii < 4; ii++) {
            int kk = ty*4 + ii;
            #pragma unroll
            for (int jj = 0; jj < 4; jj++)
                Ws[kk][tx + 32*jj] = W[(size_t)(k0 + kk)*N + n0 + tx + 32*jj];
        }
        __syncthreads();
        #pragma unroll
        for (int k = 0; k < 32; k++) {
            ulonglong2 a0 = *reinterpret_cast<const ulonglong2*>(&As[k][ry*8]);
            ulonglong2 a1 = *reinterpret_cast<const ulonglong2*>(&As[k][ry*8 + 4]);
            float4 w0 = *reinterpret_cast<const float4*>(&Ws[k][cx*8]);
            float4 w1 = *reinterpret_cast<const float4*>(&Ws[k][cx*8 + 4]);
            ull wp[8];
            wp[0] = pk2(w0.x); wp[1] = pk2(w0.y); wp[2] = pk2(w0.z); wp[3] = pk2(w0.w);
            wp[4] = pk2(w1.x); wp[5] = pk2(w1.y); wp[6] = pk2(w1.z); wp[7] = pk2(w1.w);
            #pragma unroll
            for (int c = 0; c < 8; c++) {
                acc[0][c] = fma2(a0.x, wp[c], acc[0][c]);
                acc[1][c] = fma2(a0.y, wp[c], acc[1][c]);
                acc[2][c] = fma2(a1.x, wp[c], acc[2][c]);
                acc[3][c] = fma2(a1.y, wp[c], acc[3][c]);
            }
        }
        __syncthreads();
    }
    float bv[8];
    #pragma unroll
    for (int c = 0; c < 8; c++) bv[c] = bias ? bias[n0 + cx*8 + c] : 0.f;
    #pragma unroll
    for (int p = 0; p < 4; p++) {
        int ga = m0 + ry*8 + 2*p, gb = ga + 1;
        size_t ra = remap ? (size_t)((ga & 63)*64 + (ga >> 6)) : (size_t)ga;
        size_t rb = remap ? (size_t)((gb & 63)*64 + (gb >> 6)) : (size_t)gb;
        float oa[8], ob[8];
        #pragma unroll
        for (int c = 0; c < 8; c++) {
            float lo, hi;
            unpk(acc[p][c], lo, hi);
            oa[c] = lo + bv[c];
            ob[c] = hi + bv[c];
        }
        float4* pa = reinterpret_cast<float4*>(C + ra*N + n0 + cx*8);
        float4* pb = reinterpret_cast<float4*>(C + rb*N + n0 + cx*8);
        pa[0] = make_float4(oa[0], oa[1], oa[2], oa[3]);
        pa[1] = make_float4(oa[4], oa[5], oa[6], oa[7]);
        pb[0] = make_float4(ob[0], ob[1], ob[2], ob[3]);
        pb[1] = make_float4(ob[4], ob[5], ob[6], ob[7]);
    }
}

// ================= persistent recurrence kernel ==============================

__device__ __forceinline__ void gridbar() {
    __syncthreads();
    if (threadIdx.x == 0) {
        __threadfence();
        unsigned g = g_gen;
        if (atomicAdd(&g_bar, 1u) == GRID - 1) {
            g_bar = 0;
            __threadfence();
            g_gen = g + 1;
        } else {
            while (g_gen == g) { __nanosleep(64); }
        }
        __threadfence();
    }
    __syncthreads();
}

// Gate-sliced GEMM: block computes cols [g*gw + col0, +8) for each gate g=0..2.
// K split across EIGHT 64-thread groups, f32x2, cp.async double buffering
// (8-k chunks). AT: transposed A [K][64]. Emits per-row/gate (sum,sumsq) of
// this 8-col slice into pst[gate*64*TC + row*TC] (pst pre-offset by tile id).
// sm (floats): [0,8192)  A: eighth e at e*1024 (2 bufs x 512 = 8k x 64);
//              [8192,11264) W: eighth e at 8192+e*384 (2 bufs x 192 = 8k x 24).
// Epilogue: two-stage reduction in sm[0,6144) (4 regions x 1536).
__device__ __forceinline__ void gemmG(
    const float* __restrict__ AT, int K,
    const float* __restrict__ W, int N, int gw, int col0,
    const float* __restrict__ bias, const float* __restrict__ Add,
    float* __restrict__ C, float2* __restrict__ pst, int TC,
    float* __restrict__ sm)
{
    int tid = threadIdx.x;
    int er = tid >> 6;                   // K-eighth 0..7
    int lt = tid & 63;
    int rg = lt >> 3;                    // rowgroup 0..7 (rows rg*8..+7)
    int cc = lt & 7;                     // col within 8-wide gate slice
    int Ke = K >> 3;
    int nc = Ke >> 3;                    // 8-k chunks
    const float* ATe = AT + (size_t)er * Ke * 64;
    float* Abase = sm + er * 1024;
    float* Wbase = sm + 8192 + er * 384;
    unsigned smA = (unsigned)__cvta_generic_to_shared(Abase);
    unsigned smW = (unsigned)__cvta_generic_to_shared(Wbase);

    // W transfer: 48 x 16B per chunk (8k x 3 gates x 2 4-float parts)
    int kkw = lt / 6, rw = lt - 6*kkw;   // gate = rw>>1, part = rw&1
    const float* wsrc = W + (size_t)(er*Ke + kkw)*N + (rw >> 1)*gw + col0 + (rw & 1)*4;
    unsigned wdst = smW + (unsigned)(kkw*24 + (rw >> 1)*8 + (rw & 1)*4)*4;
    bool wdo = lt < 48;

    ull acc[3][4];
    #pragma unroll
    for (int g = 0; g < 3; g++)
        #pragma unroll
        for (int j = 0; j < 4; j++) acc[g][j] = 0ull;

    // prefetch chunk 0: A 512 floats (2x16B/thr), W 192 floats
    cpa16(smA + lt*16,        ATe + (size_t)lt*4);
    cpa16(smA + (lt + 64)*16, ATe + (size_t)(lt + 64)*4);
    if (wdo) cpa16(wdst, wsrc);
    asm volatile("cp.async.commit_group;");

    for (int ch = 0; ch < nc; ch++) {
        if (ch + 1 < nc) {
            int bs = (ch + 1) & 1;
            const float* aseg = ATe + (size_t)(ch + 1) * 8 * 64;
            cpa16(smA + bs*2048 + lt*16,        aseg + (size_t)lt*4);
            cpa16(smA + bs*2048 + (lt + 64)*16, aseg + (size_t)(lt + 64)*4);
            if (wdo) cpa16(wdst + bs*768, wsrc + 8*N);
            wsrc += 8*N;
            asm volatile("cp.async.commit_group;");
            asm volatile("cp.async.wait_group 1;");
        } else {
            asm volatile("cp.async.wait_group 0;");
        }
        asm volatile("bar.sync %0, 64;" :: "r"(er + 1) : "memory");
        const float* As  = Abase + (ch & 1)*512;
        const float* Wsb = Wbase + (ch & 1)*192;
        #pragma unroll
        for (int k = 0; k < 8; k++) {
            ulonglong2 aA = *reinterpret_cast<const ulonglong2*>(As + k*64 + rg*8);
            ulonglong2 aB = *reinterpret_cast<const ulonglong2*>(As + k*64 + rg*8 + 4);
            #pragma unroll
            for (int g = 0; g < 3; g++) {
                ull w = pk2(Wsb[k*24 + g*8 + cc]);
                acc[g][0] = fma2(aA.x, w, acc[g][0]);
                acc[g][1] = fma2(aA.y, w, acc[g][1]);
                acc[g][2] = fma2(aB.x, w, acc[g][2]);
                acc[g][3] = fma2(aB.y, w, acc[g][3]);
            }
        }
        asm volatile("bar.sync %0, 64;" :: "r"(er + 1) : "memory");
    }

    // unpack partials
    float o[3][8];
    #pragma unroll
    for (int g = 0; g < 3; g++) {
        unpk(acc[g][0], o[g][0], o[g][1]);
        unpk(acc[g][1], o[g][2], o[g][3]);
        unpk(acc[g][2], o[g][4], o[g][5]);
        unpk(acc[g][3], o[g][6], o[g][7]);
    }

    // two-stage reduction: regions r=0..3 of 1536 floats at sm[r*1536]
    __syncthreads();                       // all eighths done with A/W buffers
    if (er >= 4) {
        float* R = sm + (er - 4)*1536;
        #pragma unroll
        for (int g = 0; g < 3; g++)
            #pragma unroll
            for (int i = 0; i < 8; i++)
                R[(rg*8 + i)*24 + g*8 + cc] = o[g][i];
    }
    __syncthreads();
    if (er < 4) {
        float* R = sm + er*1536;
        #pragma unroll
        for (int g = 0; g < 3; g++)
            #pragma unroll
            for (int i = 0; i < 8; i++)
                R[(rg*8 + i)*24 + g*8 + cc] += o[g][i];
    }
    __syncthreads();

    // final: 192 threads, one (gate,row) each: sum 4 regions over 8 cols,
    // +bias/+Add, store, emit LN slice stats (no shuffles).
    if (tid < 192) {
        int gate = tid >> 6, row = tid & 63;
        int base = row*24 + gate*8;
        float4 v0 = make_float4(0.f, 0.f, 0.f, 0.f);
        float4 v1 = make_float4(0.f, 0.f, 0.f, 0.f);
        #pragma unroll
        for (int r = 0; r < 4; r++) {
            float4 p0 = *reinterpret_cast<const float4*>(sm + r*1536 + base);
            float4 p1 = *reinterpret_cast<const float4*>(sm + r*1536 + base + 4);
            v0.x += p0.x; v0.y += p0.y; v0.z += p0.z; v0.w += p0.w;
            v1.x += p1.x; v1.y += p1.y; v1.z += p1.z; v1.w += p1.w;
        }
        size_t cix = (size_t)gate*gw + col0;
        if (bias) {
            float4 b0 = *reinterpret_cast<const float4*>(bias + cix);
            float4 b1 = *reinterpret_cast<const float4*>(bias + cix + 4);
            v0.x += b0.x; v0.y += b0.y; v0.z += b0.z; v0.w += b0.w;
            v1.x += b1.x; v1.y += b1.y; v1.z += b1.z; v1.w += b1.w;
        }
        if (Add) {
            float4 a0 = *reinterpret_cast<const float4*>(Add + (size_t)row*N + cix);
            float4 a1 = *reinterpret_cast<const float4*>(Add + (size_t)row*N + cix + 4);
            v0.x += a0.x; v0.y += a0.y; v0.z += a0.z; v0.w += a0.w;
            v1.x += a1.x; v1.y += a1.y; v1.z += a1.z; v1.w += a1.w;
        }
        *reinterpret_cast<float4*>(C + (size_t)row*N + cix)     = v0;
        *reinterpret_cast<float4*>(C + (size_t)row*N + cix + 4) = v1;
        float s = v0.x + v0.y + v0.z + v0.w + v1.x + v1.y + v1.z + v1.w;
        float qq = v0.x*v0.x + v0.y*v0.y + v0.z*v0.z + v0.w*v0.w
                 + v1.x*v1.x + v1.y*v1.y + v1.z*v1.z + v1.w*v1.w;
        pst[(size_t)gate*64*TC + row*TC] = make_float2(s, qq);
    }
    __syncthreads();
}

// warp-cooperative stats finalize: sum TC partials, return (mean, rstd)
__device__ __forceinline__ float2 warp_stat(const float2* __restrict__ p, int TC, float inv_hid) {
    int l = threadIdx.x & 31;
    float s = 0.f, q = 0.f;
    #pragma unroll
    for (int i = 0; i < 4; i++) {
        if (l + 32*i < TC) { s += p[l + 32*i].x; q += p[l + 32*i].y; }
    }
    #pragma unroll
    for (int o = 16; o > 0; o >>= 1) {
        s += __shfl_xor_sync(0xffffffffu, s, o);
        q += __shfl_xor_sync(0xffffffffu, q, o);
    }
    float m = s * inv_hid;
    float r = rsqrtf(q * inv_hid - m*m + 1e-5f);
    return make_float2(m, r);
}

__device__ __forceinline__ float sigm(float x) { return 1.f / (1.f + expf(-x)); }

__global__ void __launch_bounds__(TPB, 1) k_recur(
    const float* __restrict__ lWi, const float* __restrict__ lbh,
    const float* __restrict__ lWh,
    const float* __restrict__ llig, const float* __restrict__ llib,
    const float* __restrict__ llhg, const float* __restrict__ llhb,
    const float* __restrict__ hWi,  const float* __restrict__ hbi,
    const float* __restrict__ hWh,  const float* __restrict__ hbh,
    const float* __restrict__ hlig, const float* __restrict__ hlib,
    const float* __restrict__ hlhg, const float* __restrict__ hlhb)
{
    __shared__ __align__(16) float sm[11264];
    __shared__ float s_st[12];

    const float* lWi_h = lWi + (size_t)NE * 3 * NH;  // rows 768..1535 of low_Wi
    int bid = blockIdx.x, tid = threadIdx.x;
    int w = tid >> 5;
    int b = bid & 63, half = bid >> 6;
    int col0 = bid * 8;

    for (int t = 0; t < NS; t++) {
        const float* ixt = g_IX + (size_t)t * NB * 3 * NH;
        for (int c = 0; c < 3; c++) {
            // ---- phase A: HG(u=0) + ILOW (both depend only on current state)
            gemmG(g_hlT, NH, lWh, 3*NH, NH, col0, lbh, nullptr,
                  g_HG, g_psB + bid, 128, sm);
            gemmG(g_hhT, NHH, lWi_h, 3*NH, NH, col0, nullptr, ixt,
                  g_ILraw, g_psA + bid, 128, sm);
            gridbar();

            // ---- low-cell inner loop ----------------------------------------
            for (int u = 0; u < 5; u++) {
                // combine: LN(IL) + LN(HG) + gates -> h_lT
                if (w < 6) {
                    const float2* p = (w < 3)
                        ? g_psA + (size_t)w*64*128 + b*128
                        : g_psB + (size_t)(w-3)*64*128 + b*128;
                    float2 mr = warp_stat(p, 128, 1.f/NH);
                    if ((tid & 31) == 0) { s_st[2*w] = mr.x; s_st[2*w+1] = mr.y; }
                }
                __syncthreads();
                {
                    const float* Ib = g_ILraw + (size_t)b*3*NH;
                    const float* Hb = g_HG    + (size_t)b*3*NH;
                    int j = half*512 + tid;   // 512 threads cover the 512-slice
                    float i0 = (Ib[j       ] - s_st[0])*s_st[1]*llig[j       ] + llib[j       ];
                    float i1 = (Ib[NH  + j ] - s_st[2])*s_st[3]*llig[NH  + j ] + llib[NH  + j ];
                    float i2 = (Ib[2*NH + j] - s_st[4])*s_st[5]*llig[2*NH + j] + llib[2*NH + j];
                    float h0 = (Hb[j       ] - s_st[6])*s_st[7]*llhg[j       ] + llhb[j       ];
                    float h1 = (Hb[NH  + j ] - s_st[8])*s_st[9]*llhg[NH  + j ] + llhb[NH  + j ];
                    float h2 = (Hb[2*NH + j] - s_st[10])*s_st[11]*llhg[2*NH + j] + llhb[2*NH + j];
                    float r = sigm(i0 + h0);
                    float z = sigm(i1 + h1);
                    float n = tanhf(i2 + r*h2);
                    float hp = g_hlT[(size_t)j*64 + b];
                    g_hlT[(size_t)j*64 + b] = (1.f - z)*n + z*hp;
                }
                gridbar();
                if (u < 4) {
                    gemmG(g_hlT, NH, lWh, 3*NH, NH, col0, lbh, nullptr,
                          g_HG, g_psB + bid, 128, sm);
                    gridbar();
                }
            }

            // ---- high-cell GEMMs: 96 blocks, 8-col gate slices --------------
            if (bid < 96) {
                gemmG(g_hlT, NH, hWi, 3*NHH, NHH, col0, hbi, nullptr,
                      g_IHI, g_psA + bid, 96, sm);
                gemmG(g_hhT, NHH, hWh, 3*NHH, NHH, col0, hbh, nullptr,
                      g_HHG, g_psB + bid, 96, sm);
            }
            gridbar();

            // ---- high combine -> h_hT (+history at c==2) --------------------
            if (w < 6) {
                const float2* p = (w < 3)
                    ? g_psA + (size_t)w*64*96 + b*96
                    : g_psB + (size_t)(w-3)*64*96 + b*96;
                float2 mr = warp_stat(p, 96, 1.f/NHH);
                if ((tid & 31) == 0) { s_st[2*w] = mr.x; s_st[2*w+1] = mr.y; }
            }
            __syncthreads();
            if (tid < 384) {
                const float* Ib = g_IHI + (size_t)b*3*NHH;
                const float* Hb = g_HHG + (size_t)b*3*NHH;
                int j = half*384 + tid;
                float i0 = (Ib[j        ] - s_st[0])*s_st[1]*hlig[j        ] + hlib[j        ];
                float i1 = (Ib[NHH  + j ] - s_st[2])*s_st[3]*hlig[NHH  + j ] + hlib[NHH  + j ];
                float i2 = (Ib[2*NHH + j] - s_st[4])*s_st[5]*hlig[2*NHH + j] + hlib[2*NHH + j];
                float h0 = (Hb[j        ] - s_st[6])*s_st[7]*hlhg[j        ] + hlhb[j        ];
                float h1 = (Hb[NHH  + j ] - s_st[8])*s_st[9]*hlhg[NHH  + j ] + hlhb[NHH  + j ];
                float h2 = (Hb[2*NHH + j] - s_st[10])*s_st[11]*hlhg[2*NHH + j] + hlhb[2*NHH + j];
                float r = sigm(i0 + h0);
                float z = sigm(i1 + h1);
                float n = tanhf(i2 + r*h2);
                float hp = g_hhT[(size_t)j*64 + b];
                float nv = (1.f - z)*n + z*hp;
                g_hhT[(size_t)j*64 + b] = nv;
                if (c == 2) g_HH[(size_t)(t*64 + b)*NHH + j] = nv;
            }
            gridbar();
        }
    }
}

// ---------------- host orchestration ----------------------------------------
extern "C" void kernel_launch(void* const* d_in, const int* in_sizes, int n_in,
                              void* d_out, int out_size) {
    const int*   ids  = (const int*)  d_in[0];
    const float* emb  = (const float*)d_in[1];
    const float* leg  = (const float*)d_in[2];
    const float* leb  = (const float*)d_in[3];
    const float* lWi  = (const float*)d_in[4];   // [1536, 3072]
    const float* lbi  = (const float*)d_in[5];
    const float* lWh  = (const float*)d_in[6];   // [1024, 3072]
    const float* lbh  = (const float*)d_in[7];
    const float* llig = (const float*)d_in[8];
    const float* llib = (const float*)d_in[9];
    const float* llhg = (const float*)d_in[10];
    const float* llhb = (const float*)d_in[11];
    const float* hWi  = (const float*)d_in[12];  // [1024, 2304]
    const float* hbi  = (const float*)d_in[13];
    const float* hWh  = (const float*)d_in[14];  // [768, 2304]
    const float* hbh  = (const float*)d_in[15];
    const float* hlig = (const float*)d_in[16];
    const float* hlib = (const float*)d_in[17];
    const float* hlhg = (const float*)d_in[18];
    const float* hlhb = (const float*)d_in[19];
    const float* Wout = (const float*)d_in[20];  // [768, 32000]
    const float* bout = (const float*)d_in[21];
    float* out = (float*)d_out;

    float *pX, *pIX, *pHH;
    cudaGetSymbolAddress((void**)&pX,  g_X);
    cudaGetSymbolAddress((void**)&pIX, g_IX);
    cudaGetSymbolAddress((void**)&pHH, g_HH);

    // zero hidden states (transposed layouts)
    k_init<<<256, 256>>>();

    // x = LN(emb[ids]) laid out [S, B, E]
    k_embed<<<NB*NS, 256>>>(ids, emb, leg, leb);

    // IX = x @ Wi_x + bi for ALL tokens up front (reused 15x per step)
    k_gemm_big<<<dim3((3*NH)/128, (NB*NS)/128), 256>>>(pX, lWi, lbi, pIX, NE, 3*NH, 0);

    // full recurrence in ONE persistent kernel (software grid barriers)
    k_recur<<<GRID, TPB>>>(lWi, lbh, lWh,
                           llig, llib, llhg, llhb,
                           hWi, hbi, hWh, hbh,
                           hlig, hlib, hlhg, hlhb);

    // logits = h_h_hist @ Wout + bout, row remap (s*64+b) -> out[(b*64+s)*V]
    k_gemm_big<<<dim3(NV/128, (NB*NS)/128), 256>>>(pHH, Wout, bout, out, NHH, NV, 1);
}